// round 1
// baseline (speedup 1.0000x reference)
#include <cuda_runtime.h>
#include <cuda_bf16.h>
#include <math.h>

// Problem constants (match reference)
#define NNODES 50000
#define NEDGES 400000
#define NGRAPH 64
#define NHEAD  4
#define F1 256
#define F2 128

// ---------------------------------------------------------------------------
// Device scratch (allowed: __device__ globals, no dynamic allocation)
// ---------------------------------------------------------------------------
__device__ float g_h[NNODES * F1];          // projected features (max F = 256)
__device__ float g_out0[NNODES * F1];       // relation-0 aggregated output
__device__ float g_out1[NNODES * F1];       // relation-1 aggregated output
__device__ float g_comb1[NNODES * F1];      // layer-1 combined output
__device__ float g_comb2[NNODES * F2];      // layer-2 combined output
__device__ float g_s[NNODES * NHEAD];
__device__ float g_dd[NNODES * NHEAD];
__device__ float g_amax[NNODES * NHEAD];
__device__ float g_den[NNODES * NHEAD];
__device__ float g_alpha[NEDGES * NHEAD];
__device__ float g_wsum[2 * F1];
__device__ float g_attn[2];
__device__ float g_pool[NGRAPH * F2];
__device__ float g_cnt[NGRAPH];

// ---------------------------------------------------------------------------
// Helpers
// ---------------------------------------------------------------------------
__device__ __forceinline__ void atomicMaxF(float* addr, float val) {
    int old = __float_as_int(*addr);
    while (__int_as_float(old) < val) {
        int assumed = old;
        old = atomicCAS((int*)addr, assumed, __float_as_int(val));
        if (old == assumed) break;
    }
}

__global__ void fillk(float* __restrict__ p, float v, long n) {
    long i = (long)blockIdx.x * blockDim.x + threadIdx.x;
    if (i < n) p[i] = v;
}

// ---------------------------------------------------------------------------
// SGEMM: C[M,F] = A[M,K] @ W[K,F] (+bias). mode 0: write C+bias.
// mode 1: colsum[f] += sum_m tanh(acc + bias[f])   (no C write)
// BM=BN=64, BK=16, 256 threads, 4x4 micro-tile.
// Requires K % 16 == 0, F % 64 == 0 (true here: K in {128,256}, F in {128,256}).
// ---------------------------------------------------------------------------
#define BM 64
#define BN 64
#define BKK 16
__global__ __launch_bounds__(256) void sgemm_kernel(
    const float* __restrict__ A, const float* __restrict__ W,
    const float* __restrict__ bias, float* __restrict__ C,
    int M, int K, int F, int mode, float* __restrict__ colsum)
{
    __shared__ float As[BKK][BM + 1];
    __shared__ float Ws[BKK][BN];

    int tid  = threadIdx.x;
    int tcol = tid & 15;       // 0..15
    int trow = tid >> 4;       // 0..15
    int rowBase = blockIdx.y * BM;
    int colBase = blockIdx.x * BN;

    float acc[4][4];
#pragma unroll
    for (int i = 0; i < 4; i++)
#pragma unroll
        for (int j = 0; j < 4; j++) acc[i][j] = 0.f;

    for (int k0 = 0; k0 < K; k0 += BKK) {
        // load A tile (64 rows x 16 cols), store transposed
#pragma unroll
        for (int i = 0; i < 4; i++) {
            int idx = tid + i * 256;
            int r = idx >> 4;            // 0..63
            int c = idx & 15;            // 0..15
            int gr = rowBase + r;
            As[c][r] = (gr < M) ? A[(size_t)gr * K + k0 + c] : 0.f;
        }
        // load W tile (16 rows x 64 cols)
#pragma unroll
        for (int i = 0; i < 4; i++) {
            int idx = tid + i * 256;
            int r = idx >> 6;            // 0..15
            int c = idx & 63;            // 0..63
            Ws[r][c] = W[(size_t)(k0 + r) * F + colBase + c];
        }
        __syncthreads();
#pragma unroll
        for (int k = 0; k < BKK; k++) {
            float a[4], b[4];
#pragma unroll
            for (int i = 0; i < 4; i++) a[i] = As[k][trow * 4 + i];
#pragma unroll
            for (int j = 0; j < 4; j++) b[j] = Ws[k][tcol * 4 + j];
#pragma unroll
            for (int i = 0; i < 4; i++)
#pragma unroll
                for (int j = 0; j < 4; j++) acc[i][j] += a[i] * b[j];
        }
        __syncthreads();
    }

    if (mode == 0) {
#pragma unroll
        for (int i = 0; i < 4; i++) {
            int gr = rowBase + trow * 4 + i;
            if (gr >= M) continue;
#pragma unroll
            for (int j = 0; j < 4; j++) {
                int gc = colBase + tcol * 4 + j;
                C[(size_t)gr * F + gc] = acc[i][j] + bias[gc];
            }
        }
    } else {
        float cs[4] = {0.f, 0.f, 0.f, 0.f};
#pragma unroll
        for (int i = 0; i < 4; i++) {
            int gr = rowBase + trow * 4 + i;
            if (gr >= M) continue;
#pragma unroll
            for (int j = 0; j < 4; j++) {
                int gc = colBase + tcol * 4 + j;
                cs[j] += tanhf(acc[i][j] + bias[gc]);
            }
        }
#pragma unroll
        for (int j = 0; j < 4; j++) {
            int gc = colBase + tcol * 4 + j;
            atomicAdd(&colsum[gc], cs[j]);
        }
    }
}

// ---------------------------------------------------------------------------
// Per-(node,head) attention scores: s = <h[n,h,:], a_src[h,:]>, d likewise
// ---------------------------------------------------------------------------
__global__ void node_scores_kernel(const float* __restrict__ h,
                                   const float* __restrict__ asrc,
                                   const float* __restrict__ adst,
                                   float* __restrict__ s, float* __restrict__ d,
                                   int n, int F, int D)
{
    int idx = blockIdx.x * blockDim.x + threadIdx.x;
    if (idx >= n * NHEAD) return;
    int node = idx / NHEAD;
    int hh   = idx % NHEAD;
    const float* hp = h + (size_t)node * F + hh * D;
    const float* ap = asrc + hh * D;
    const float* bp = adst + hh * D;
    float ss = 0.f, dd = 0.f;
    for (int i = 0; i < D; i++) {
        float v = hp[i];
        ss += v * ap[i];
        dd += v * bp[i];
    }
    s[idx] = ss;
    d[idx] = dd;
}

// ---------------------------------------------------------------------------
// alpha = leaky_relu(s[src]+d[dst], 0.2); segment max over dst
// ---------------------------------------------------------------------------
__global__ void edge_alpha_kernel(const int* __restrict__ ei,
                                  const float* __restrict__ s,
                                  const float* __restrict__ d,
                                  float* __restrict__ alpha,
                                  float* __restrict__ amax, int E)
{
    int idx = blockIdx.x * blockDim.x + threadIdx.x;
    if (idx >= E * NHEAD) return;
    int e  = idx >> 2;
    int hh = idx & 3;
    int src = __ldg(&ei[e]);
    int dst = __ldg(&ei[E + e]);
    float v = s[src * NHEAD + hh] + d[dst * NHEAD + hh];
    v = (v >= 0.f) ? v : 0.2f * v;
    alpha[idx] = v;
    atomicMaxF(&amax[dst * NHEAD + hh], v);
}

__global__ void edge_exp_kernel(const int* __restrict__ ei,
                                float* __restrict__ alpha,
                                const float* __restrict__ amax,
                                float* __restrict__ den, int E)
{
    int idx = blockIdx.x * blockDim.x + threadIdx.x;
    if (idx >= E * NHEAD) return;
    int e  = idx >> 2;
    int hh = idx & 3;
    int dst = __ldg(&ei[E + e]);
    float ex = expf(alpha[idx] - amax[dst * NHEAD + hh]);
    alpha[idx] = ex;
    atomicAdd(&den[dst * NHEAD + hh], ex);
}

// ---------------------------------------------------------------------------
// Gather h[src], scale by normalized alpha, scatter-add to out[dst]
// One block per edge, F threads.
// ---------------------------------------------------------------------------
__global__ void scatter_kernel(const int* __restrict__ ei,
                               const float* __restrict__ h,
                               const float* __restrict__ alpha,
                               const float* __restrict__ den,
                               float* __restrict__ out, int E, int F, int D)
{
    int e = blockIdx.x;
    int f = threadIdx.x;
    int src = __ldg(&ei[e]);
    int dst = __ldg(&ei[E + e]);
    int hh  = f / D;
    float a  = __ldg(&alpha[e * NHEAD + hh]);
    float dn = __ldg(&den[dst * NHEAD + hh]);
    float val = __ldg(&h[(size_t)src * F + f]) * (a / (dn + 1e-16f));
    atomicAdd(&out[(size_t)dst * F + f], val);
}

__global__ void relu_kernel(float* __restrict__ p, long n) {
    long i = (long)blockIdx.x * blockDim.x + threadIdx.x;
    if (i < n) p[i] = fmaxf(p[i], 0.f);
}

// ---------------------------------------------------------------------------
// Semantic attention: w_r = wsum_r / N; attn = softmax_r( <w_r, q> )
// ---------------------------------------------------------------------------
__global__ void semantic_kernel(const float* __restrict__ wsum,
                                const float* __restrict__ q,
                                float* __restrict__ attn, int F, float invN)
{
    __shared__ float sh0[256], sh1[256];
    int t = threadIdx.x;
    float p0 = 0.f, p1 = 0.f;
    for (int f = t; f < F; f += 256) {
        float qf = q[f];
        p0 += wsum[f] * invN * qf;
        p1 += wsum[F + f] * invN * qf;
    }
    sh0[t] = p0; sh1[t] = p1;
    __syncthreads();
    for (int s = 128; s > 0; s >>= 1) {
        if (t < s) { sh0[t] += sh0[t + s]; sh1[t] += sh1[t + s]; }
        __syncthreads();
    }
    if (t == 0) {
        float m  = fmaxf(sh0[0], sh1[0]);
        float e0 = expf(sh0[0] - m);
        float e1 = expf(sh1[0] - m);
        float inv = 1.f / (e0 + e1);
        attn[0] = e0 * inv;
        attn[1] = e1 * inv;
    }
}

__global__ void combine_kernel(const float* __restrict__ o0,
                               const float* __restrict__ o1,
                               const float* __restrict__ attn,
                               float* __restrict__ outp, long n)
{
    long i = (long)blockIdx.x * blockDim.x + threadIdx.x;
    if (i < n) outp[i] = attn[0] * o0[i] + attn[1] * o1[i];
}

// ---------------------------------------------------------------------------
// Pooling + MLP head
// ---------------------------------------------------------------------------
__global__ void pool_kernel(const float* __restrict__ xin,
                            const int* __restrict__ batch,
                            float* __restrict__ pool, int n, int F)
{
    long i = (long)blockIdx.x * blockDim.x + threadIdx.x;
    if (i >= (long)n * F) return;
    int node = (int)(i / F);
    int f    = (int)(i % F);
    atomicAdd(&pool[batch[node] * F + f], xin[i]);
}

__global__ void count_kernel(const int* __restrict__ batch,
                             float* __restrict__ cnt, int n)
{
    int i = blockIdx.x * blockDim.x + threadIdx.x;
    if (i < n) atomicAdd(&cnt[batch[i]], 1.f);
}

__global__ void head_kernel(const float* __restrict__ pool,
                            const float* __restrict__ cnt,
                            const float* __restrict__ d1w,  // [128,64]
                            const float* __restrict__ d1b,
                            const float* __restrict__ gma,
                            const float* __restrict__ bta,
                            const float* __restrict__ mean,
                            const float* __restrict__ var,
                            const float* __restrict__ d2w,  // [64,1]
                            const float* __restrict__ d2b,
                            float* __restrict__ out)
{
    int g = blockIdx.x;          // graph
    int j = threadIdx.x;         // hidden unit 0..63
    float c = fmaxf(cnt[g], 1.f);
    float inv = 1.f / c;
    float acc = d1b[j];
    for (int k = 0; k < F2; k++)
        acc += (pool[g * F2 + k] * inv) * d1w[k * 64 + j];
    acc = (acc - mean[j]) * rsqrtf(var[j] + 1e-5f) * gma[j] + bta[j];
    acc = (acc >= 0.f) ? acc : 0.1f * acc;
    float v = acc * d2w[j];
    __shared__ float red[64];
    red[j] = v;
    __syncthreads();
    for (int s = 32; s > 0; s >>= 1) {
        if (j < s) red[j] += red[j + s];
        __syncthreads();
    }
    if (j == 0) out[g] = red[0] + d2b[0];
}

// ---------------------------------------------------------------------------
// Host orchestration
// ---------------------------------------------------------------------------
static inline int cdiv(long a, int b) { return (int)((a + b - 1) / b); }

static void run_layer(const float* X, int inF, int F, int D,
                      const float* projW, const float* projB,
                      const float* as0, const float* ad0,
                      const float* as1, const float* ad1,
                      const float* klinW, const float* klinB, const float* q,
                      const int* ei0, const int* ei1,
                      float* h, float* out0, float* out1, float* comb,
                      float* s, float* d, float* amax, float* den,
                      float* alpha, float* wsum, float* attn)
{
    const int n = NNODES, E = NEDGES;
    const long nF = (long)n * F;

    fillk<<<cdiv(2 * F, 256), 256>>>(wsum, 0.f, 2 * F);

    // projection GEMM
    {
        dim3 grid(F / 64, cdiv(n, 64));
        sgemm_kernel<<<grid, 256>>>(X, projW, projB, h, n, inF, F, 0, nullptr);
    }

    const float* as_[2] = {as0, as1};
    const float* ad_[2] = {ad0, ad1};
    const int*   ei_[2] = {ei0, ei1};
    float*       outp[2] = {out0, out1};

    for (int r = 0; r < 2; r++) {
        node_scores_kernel<<<cdiv((long)n * NHEAD, 256), 256>>>(
            h, as_[r], ad_[r], s, d, n, F, D);
        fillk<<<cdiv((long)n * NHEAD, 256), 256>>>(amax, -INFINITY, (long)n * NHEAD);
        fillk<<<cdiv((long)n * NHEAD, 256), 256>>>(den, 0.f, (long)n * NHEAD);
        fillk<<<cdiv(nF, 256), 256>>>(outp[r], 0.f, nF);
        edge_alpha_kernel<<<cdiv((long)E * NHEAD, 256), 256>>>(
            ei_[r], s, d, alpha, amax, E);
        edge_exp_kernel<<<cdiv((long)E * NHEAD, 256), 256>>>(
            ei_[r], alpha, amax, den, E);
        scatter_kernel<<<E, F>>>(ei_[r], h, alpha, den, outp[r], E, F, D);
        relu_kernel<<<cdiv(nF, 256), 256>>>(outp[r], nF);
        // semantic GEMM: colsum of tanh(out_r @ klin + b)
        dim3 grid(F / 64, cdiv(n, 64));
        sgemm_kernel<<<grid, 256>>>(outp[r], klinW, klinB, nullptr,
                                    n, F, F, 1, wsum + r * F);
    }

    semantic_kernel<<<1, 256>>>(wsum, q, attn, F, 1.f / n);
    combine_kernel<<<cdiv(nF, 256), 256>>>(out0, out1, attn, comb, nF);
}

extern "C" void kernel_launch(void* const* d_in, const int* in_sizes, int n_in,
                              void* d_out, int out_size)
{
    const float* x       = (const float*)d_in[0];
    const int*   ei0     = (const int*)d_in[1];
    const int*   ei1     = (const int*)d_in[2];
    const int*   batch   = (const int*)d_in[3];
    const float* proj1_w = (const float*)d_in[4];
    const float* proj1_b = (const float*)d_in[5];
    const float* as1_r0  = (const float*)d_in[6];
    const float* ad1_r0  = (const float*)d_in[7];
    const float* as1_r1  = (const float*)d_in[8];
    const float* ad1_r1  = (const float*)d_in[9];
    const float* klin1_w = (const float*)d_in[10];
    const float* klin1_b = (const float*)d_in[11];
    const float* q1      = (const float*)d_in[12];
    const float* proj2_w = (const float*)d_in[13];
    const float* proj2_b = (const float*)d_in[14];
    const float* as2_r0  = (const float*)d_in[15];
    const float* ad2_r0  = (const float*)d_in[16];
    const float* as2_r1  = (const float*)d_in[17];
    const float* ad2_r1  = (const float*)d_in[18];
    const float* klin2_w = (const float*)d_in[19];
    const float* klin2_b = (const float*)d_in[20];
    const float* q2      = (const float*)d_in[21];
    const float* d1_w    = (const float*)d_in[22];
    const float* d1_b    = (const float*)d_in[23];
    const float* bn_g    = (const float*)d_in[24];
    const float* bn_b    = (const float*)d_in[25];
    const float* bn_m    = (const float*)d_in[26];
    const float* bn_v    = (const float*)d_in[27];
    const float* d2_w    = (const float*)d_in[28];
    const float* d2_b    = (const float*)d_in[29];
    float* out = (float*)d_out;

    float *h, *o0, *o1, *c1, *c2, *s, *d, *amax, *den, *alpha, *wsum, *attn,
          *pool, *cnt;
    cudaGetSymbolAddress((void**)&h,     g_h);
    cudaGetSymbolAddress((void**)&o0,    g_out0);
    cudaGetSymbolAddress((void**)&o1,    g_out1);
    cudaGetSymbolAddress((void**)&c1,    g_comb1);
    cudaGetSymbolAddress((void**)&c2,    g_comb2);
    cudaGetSymbolAddress((void**)&s,     g_s);
    cudaGetSymbolAddress((void**)&d,     g_dd);
    cudaGetSymbolAddress((void**)&amax,  g_amax);
    cudaGetSymbolAddress((void**)&den,   g_den);
    cudaGetSymbolAddress((void**)&alpha, g_alpha);
    cudaGetSymbolAddress((void**)&wsum,  g_wsum);
    cudaGetSymbolAddress((void**)&attn,  g_attn);
    cudaGetSymbolAddress((void**)&pool,  g_pool);
    cudaGetSymbolAddress((void**)&cnt,   g_cnt);

    // Layer 1: 128 -> 256 (H=4, D=64)
    run_layer(x, 128, F1, 64,
              proj1_w, proj1_b, as1_r0, ad1_r0, as1_r1, ad1_r1,
              klin1_w, klin1_b, q1, ei0, ei1,
              h, o0, o1, c1, s, d, amax, den, alpha, wsum, attn);

    // Layer 2: 256 -> 128 (H=4, D=32)
    run_layer(c1, F1, F2, 32,
              proj2_w, proj2_b, as2_r0, ad2_r0, as2_r1, ad2_r1,
              klin2_w, klin2_b, q2, ei0, ei1,
              h, o0, o1, c2, s, d, amax, den, alpha, wsum, attn);

    // Global mean pool + MLP head
    fillk<<<cdiv(NGRAPH * F2, 256), 256>>>(pool, 0.f, NGRAPH * F2);
    fillk<<<1, 64>>>(cnt, 0.f, NGRAPH);
    pool_kernel<<<cdiv((long)NNODES * F2, 256), 256>>>(c2, batch, pool, NNODES, F2);
    count_kernel<<<cdiv(NNODES, 256), 256>>>(batch, cnt, NNODES);
    head_kernel<<<NGRAPH, 64>>>(pool, cnt, d1_w, d1_b, bn_g, bn_b, bn_m, bn_v,
                                d2_w, d2_b, out);
}

// round 3
// speedup vs baseline: 1.4369x; 1.4369x over previous
#include <cuda_runtime.h>
#include <cuda_bf16.h>
#include <math.h>

// Problem constants (match reference)
#define NNODES 50000
#define NEDGES 400000
#define NGRAPH 64
#define NHEAD  4
#define F1 256
#define F2 128

// ---------------------------------------------------------------------------
// Device scratch
// ---------------------------------------------------------------------------
__device__ float g_h[NNODES * F1];
__device__ float g_out0[NNODES * F1];
__device__ float g_out1[NNODES * F1];
__device__ float g_comb1[NNODES * F1];
__device__ float g_comb2[NNODES * F2];
__device__ float g_s[NNODES * NHEAD];
__device__ float g_dd[NNODES * NHEAD];
__device__ float g_amax[NNODES * NHEAD];
__device__ float g_den[NNODES * NHEAD];
__device__ float g_alpha[NEDGES * NHEAD];
__device__ float g_wsum[2 * F1];
__device__ float g_attn[2];
__device__ float g_pool[NGRAPH * F2];
__device__ float g_cnt[NGRAPH];

// ---------------------------------------------------------------------------
// Helpers
// ---------------------------------------------------------------------------
__device__ __forceinline__ void atomicMaxF(float* addr, float val) {
    int old = __float_as_int(*addr);
    while (__int_as_float(old) < val) {
        int assumed = old;
        old = atomicCAS((int*)addr, assumed, __float_as_int(val));
        if (old == assumed) break;
    }
}

// tf32 round-to-nearest; returns raw bits (cvt.*.tf32 needs .b32 dst operand)
__device__ __forceinline__ unsigned to_tf32_bits(float x) {
    unsigned r;
    asm("cvt.rna.tf32.f32 %0, %1;" : "=r"(r) : "f"(x));
    return r;
}
__device__ __forceinline__ float to_tf32(float x) {
    return __uint_as_float(to_tf32_bits(x));
}

__device__ __forceinline__ void mma_tf32(float c[4],
                                         const unsigned a[4],
                                         const unsigned b[2]) {
    asm volatile(
        "mma.sync.aligned.m16n8k8.row.col.f32.tf32.tf32.f32 "
        "{%0,%1,%2,%3}, {%4,%5,%6,%7}, {%8,%9}, {%0,%1,%2,%3};"
        : "+f"(c[0]), "+f"(c[1]), "+f"(c[2]), "+f"(c[3])
        : "r"(a[0]), "r"(a[1]), "r"(a[2]), "r"(a[3]),
          "r"(b[0]), "r"(b[1]));
}

__global__ void fillk(float* __restrict__ p, float v, long n) {
    long i = (long)blockIdx.x * blockDim.x + threadIdx.x;
    if (i < n) p[i] = v;
}

// ---------------------------------------------------------------------------
// TF32 tensor-core GEMM: C[M,F] = A[M,K] @ W[K,F] (+bias)
// mode 0: write C = acc + bias
// mode 1: colsum[f] += sum_m tanh(acc + bias[f]); optional relu on A input
// Tile: BM=128, BN=128, BK=16. 256 threads = 8 warps (2x4), warp tile 64x32.
// Requires K % 16 == 0, F % 128 == 0 (true: K,F in {128,256}).
// ---------------------------------------------------------------------------
#define GBM 128
#define GBN 128
#define GBK 16
#define A_STRIDE 20
#define B_STRIDE 136

__global__ __launch_bounds__(256) void mma_gemm(
    const float* __restrict__ A, const float* __restrict__ W,
    const float* __restrict__ bias, float* __restrict__ C,
    int M, int K, int F, int mode, int relu_in, float* __restrict__ colsum)
{
    __shared__ float As[2][GBM][A_STRIDE];   // 2*128*20*4 = 20480 B
    __shared__ float Bs[2][GBK][B_STRIDE];   // 2*16*136*4 = 17408 B

    const int tid  = threadIdx.x;
    const int lane = tid & 31;
    const int warp = tid >> 5;
    const int wm   = warp & 1;    // 0..1  (64-row slabs)
    const int wn   = warp >> 1;   // 0..3  (32-col slabs)
    const int gid  = lane >> 2;   // 0..7
    const int tig  = lane & 3;    // 0..3

    const int rowBase = blockIdx.y * GBM;
    const int colBase = blockIdx.x * GBN;

    float acc[4][4][4];
#pragma unroll
    for (int mt = 0; mt < 4; mt++)
#pragma unroll
        for (int nt = 0; nt < 4; nt++)
#pragma unroll
            for (int i = 0; i < 4; i++) acc[mt][nt][i] = 0.f;

    // global-load index mapping (per thread: 2x float4 for A, 2x float4 for B)
    const int a_r0 = tid >> 2;            // 0..63
    const int a_c0 = (tid & 3) * 4;       // 0,4,8,12
    const int b_k0 = tid >> 5;            // 0..7
    const int b_c0 = (tid & 31) * 4;      // 0..124

    const int KT = K / GBK;

    float4 ra[2], rb[2];

    // ---- load tile 0 into regs + smem buf 0 ----
    {
        const int k0 = 0;
#pragma unroll
        for (int i = 0; i < 2; i++) {
            int r = a_r0 + i * 64;
            int gr = rowBase + r;
            if (gr < M) {
                ra[i] = *reinterpret_cast<const float4*>(&A[(size_t)gr * K + k0 + a_c0]);
                if (relu_in) {
                    ra[i].x = fmaxf(ra[i].x, 0.f); ra[i].y = fmaxf(ra[i].y, 0.f);
                    ra[i].z = fmaxf(ra[i].z, 0.f); ra[i].w = fmaxf(ra[i].w, 0.f);
                }
            } else ra[i] = make_float4(0.f, 0.f, 0.f, 0.f);
            int kr = b_k0 + i * 8;
            rb[i] = *reinterpret_cast<const float4*>(&W[(size_t)(k0 + kr) * F + colBase + b_c0]);
        }
#pragma unroll
        for (int i = 0; i < 2; i++) {
            float4 v;
            v.x = to_tf32(ra[i].x); v.y = to_tf32(ra[i].y);
            v.z = to_tf32(ra[i].z); v.w = to_tf32(ra[i].w);
            *reinterpret_cast<float4*>(&As[0][a_r0 + i * 64][a_c0]) = v;
            float4 w;
            w.x = to_tf32(rb[i].x); w.y = to_tf32(rb[i].y);
            w.z = to_tf32(rb[i].z); w.w = to_tf32(rb[i].w);
            *reinterpret_cast<float4*>(&Bs[0][b_k0 + i * 8][b_c0]) = w;
        }
    }
    __syncthreads();

    for (int kt = 0; kt < KT; kt++) {
        const int buf = kt & 1;
        // prefetch next tile into regs
        if (kt + 1 < KT) {
            const int k0 = (kt + 1) * GBK;
#pragma unroll
            for (int i = 0; i < 2; i++) {
                int r = a_r0 + i * 64;
                int gr = rowBase + r;
                if (gr < M) {
                    ra[i] = *reinterpret_cast<const float4*>(&A[(size_t)gr * K + k0 + a_c0]);
                    if (relu_in) {
                        ra[i].x = fmaxf(ra[i].x, 0.f); ra[i].y = fmaxf(ra[i].y, 0.f);
                        ra[i].z = fmaxf(ra[i].z, 0.f); ra[i].w = fmaxf(ra[i].w, 0.f);
                    }
                } else ra[i] = make_float4(0.f, 0.f, 0.f, 0.f);
                int kr = b_k0 + i * 8;
                rb[i] = *reinterpret_cast<const float4*>(&W[(size_t)(k0 + kr) * F + colBase + b_c0]);
            }
        }
        // compute on current buffer: 2 k-steps of 8
#pragma unroll
        for (int ks = 0; ks < 2; ks++) {
            const int kb = ks * 8;
            unsigned afr[4][4], bfr[4][2];
#pragma unroll
            for (int mt = 0; mt < 4; mt++) {
                int r = wm * 64 + mt * 16 + gid;
                afr[mt][0] = __float_as_uint(As[buf][r][kb + tig]);
                afr[mt][1] = __float_as_uint(As[buf][r + 8][kb + tig]);
                afr[mt][2] = __float_as_uint(As[buf][r][kb + tig + 4]);
                afr[mt][3] = __float_as_uint(As[buf][r + 8][kb + tig + 4]);
            }
#pragma unroll
            for (int nt = 0; nt < 4; nt++) {
                int c = wn * 32 + nt * 8 + gid;
                bfr[nt][0] = __float_as_uint(Bs[buf][kb + tig][c]);
                bfr[nt][1] = __float_as_uint(Bs[buf][kb + tig + 4][c]);
            }
#pragma unroll
            for (int mt = 0; mt < 4; mt++)
#pragma unroll
                for (int nt = 0; nt < 4; nt++)
                    mma_tf32(acc[mt][nt], afr[mt], bfr[nt]);
        }
        if (kt + 1 < KT) {
            const int nbuf = (kt + 1) & 1;
#pragma unroll
            for (int i = 0; i < 2; i++) {
                float4 v;
                v.x = to_tf32(ra[i].x); v.y = to_tf32(ra[i].y);
                v.z = to_tf32(ra[i].z); v.w = to_tf32(ra[i].w);
                *reinterpret_cast<float4*>(&As[nbuf][a_r0 + i * 64][a_c0]) = v;
                float4 w;
                w.x = to_tf32(rb[i].x); w.y = to_tf32(rb[i].y);
                w.z = to_tf32(rb[i].z); w.w = to_tf32(rb[i].w);
                *reinterpret_cast<float4*>(&Bs[nbuf][b_k0 + i * 8][b_c0]) = w;
            }
            __syncthreads();
        }
    }

    // ---- epilogue ----
    if (mode == 0) {
#pragma unroll
        for (int mt = 0; mt < 4; mt++) {
            int r0 = rowBase + wm * 64 + mt * 16 + gid;
            int r1 = r0 + 8;
#pragma unroll
            for (int nt = 0; nt < 4; nt++) {
                int gc = colBase + wn * 32 + nt * 8 + tig * 2;
                float b0 = bias[gc], b1 = bias[gc + 1];
                if (r0 < M) {
                    float2 v = make_float2(acc[mt][nt][0] + b0, acc[mt][nt][1] + b1);
                    *reinterpret_cast<float2*>(&C[(size_t)r0 * F + gc]) = v;
                }
                if (r1 < M) {
                    float2 v = make_float2(acc[mt][nt][2] + b0, acc[mt][nt][3] + b1);
                    *reinterpret_cast<float2*>(&C[(size_t)r1 * F + gc]) = v;
                }
            }
        }
    } else {
#pragma unroll
        for (int nt = 0; nt < 4; nt++) {
            int gc = colBase + wn * 32 + nt * 8 + tig * 2;
            float b0 = bias[gc], b1 = bias[gc + 1];
            float csA = 0.f, csB = 0.f;
#pragma unroll
            for (int mt = 0; mt < 4; mt++) {
                int r0 = rowBase + wm * 64 + mt * 16 + gid;
                int r1 = r0 + 8;
                if (r0 < M) {
                    csA += tanhf(acc[mt][nt][0] + b0);
                    csB += tanhf(acc[mt][nt][1] + b1);
                }
                if (r1 < M) {
                    csA += tanhf(acc[mt][nt][2] + b0);
                    csB += tanhf(acc[mt][nt][3] + b1);
                }
            }
            atomicAdd(&colsum[gc], csA);
            atomicAdd(&colsum[gc + 1], csB);
        }
    }
}

// ---------------------------------------------------------------------------
// Per-(node,head) attention scores
// ---------------------------------------------------------------------------
__global__ void node_scores_kernel(const float* __restrict__ h,
                                   const float* __restrict__ asrc,
                                   const float* __restrict__ adst,
                                   float* __restrict__ s, float* __restrict__ d,
                                   int n, int F, int D)
{
    int idx = blockIdx.x * blockDim.x + threadIdx.x;
    if (idx >= n * NHEAD) return;
    int node = idx / NHEAD;
    int hh   = idx % NHEAD;
    const float* hp = h + (size_t)node * F + hh * D;
    const float* ap = asrc + hh * D;
    const float* bp = adst + hh * D;
    float ss = 0.f, dd = 0.f;
    for (int i = 0; i < D; i++) {
        float v = hp[i];
        ss += v * ap[i];
        dd += v * bp[i];
    }
    s[idx] = ss;
    d[idx] = dd;
}

// ---------------------------------------------------------------------------
// Edge kernels
// ---------------------------------------------------------------------------
__global__ void edge_alpha_kernel(const int* __restrict__ ei,
                                  const float* __restrict__ s,
                                  const float* __restrict__ d,
                                  float* __restrict__ alpha,
                                  float* __restrict__ amax, int E)
{
    int idx = blockIdx.x * blockDim.x + threadIdx.x;
    if (idx >= E * NHEAD) return;
    int e  = idx >> 2;
    int hh = idx & 3;
    int src = __ldg(&ei[e]);
    int dst = __ldg(&ei[E + e]);
    float v = s[src * NHEAD + hh] + d[dst * NHEAD + hh];
    v = (v >= 0.f) ? v : 0.2f * v;
    alpha[idx] = v;
    atomicMaxF(&amax[dst * NHEAD + hh], v);
}

__global__ void edge_exp_kernel(const int* __restrict__ ei,
                                float* __restrict__ alpha,
                                const float* __restrict__ amax,
                                float* __restrict__ den, int E)
{
    int idx = blockIdx.x * blockDim.x + threadIdx.x;
    if (idx >= E * NHEAD) return;
    int e  = idx >> 2;
    int hh = idx & 3;
    int dst = __ldg(&ei[E + e]);
    float ex = expf(alpha[idx] - amax[dst * NHEAD + hh]);
    alpha[idx] = ex;
    atomicAdd(&den[dst * NHEAD + hh], ex);
}

__global__ void scatter_kernel(const int* __restrict__ ei,
                               const float* __restrict__ h,
                               const float* __restrict__ alpha,
                               const float* __restrict__ den,
                               float* __restrict__ out, int E, int F, int D)
{
    int e = blockIdx.x;
    int f = threadIdx.x;
    int src = __ldg(&ei[e]);
    int dst = __ldg(&ei[E + e]);
    int hh  = f / D;
    float a  = __ldg(&alpha[e * NHEAD + hh]);
    float dn = __ldg(&den[dst * NHEAD + hh]);
    float val = __ldg(&h[(size_t)src * F + f]) * (a / (dn + 1e-16f));
    atomicAdd(&out[(size_t)dst * F + f], val);
}

// ---------------------------------------------------------------------------
// Semantic attention + combine (combine applies relu to inputs)
// ---------------------------------------------------------------------------
__global__ void semantic_kernel(const float* __restrict__ wsum,
                                const float* __restrict__ q,
                                float* __restrict__ attn, int F, float invN)
{
    __shared__ float sh0[256], sh1[256];
    int t = threadIdx.x;
    float p0 = 0.f, p1 = 0.f;
    for (int f = t; f < F; f += 256) {
        float qf = q[f];
        p0 += wsum[f] * invN * qf;
        p1 += wsum[F + f] * invN * qf;
    }
    sh0[t] = p0; sh1[t] = p1;
    __syncthreads();
    for (int s = 128; s > 0; s >>= 1) {
        if (t < s) { sh0[t] += sh0[t + s]; sh1[t] += sh1[t + s]; }
        __syncthreads();
    }
    if (t == 0) {
        float m  = fmaxf(sh0[0], sh1[0]);
        float e0 = expf(sh0[0] - m);
        float e1 = expf(sh1[0] - m);
        float inv = 1.f / (e0 + e1);
        attn[0] = e0 * inv;
        attn[1] = e1 * inv;
    }
}

__global__ void combine_kernel(const float* __restrict__ o0,
                               const float* __restrict__ o1,
                               const float* __restrict__ attn,
                               float* __restrict__ outp, long n)
{
    long i = (long)blockIdx.x * blockDim.x + threadIdx.x;
    if (i < n)
        outp[i] = attn[0] * fmaxf(o0[i], 0.f) + attn[1] * fmaxf(o1[i], 0.f);
}

// ---------------------------------------------------------------------------
// Pooling + MLP head
// ---------------------------------------------------------------------------
__global__ void pool_kernel(const float* __restrict__ xin,
                            const int* __restrict__ batch,
                            float* __restrict__ pool, int n, int F)
{
    long i = (long)blockIdx.x * blockDim.x + threadIdx.x;
    if (i >= (long)n * F) return;
    int node = (int)(i / F);
    int f    = (int)(i % F);
    atomicAdd(&pool[batch[node] * F + f], xin[i]);
}

__global__ void count_kernel(const int* __restrict__ batch,
                             float* __restrict__ cnt, int n)
{
    int i = blockIdx.x * blockDim.x + threadIdx.x;
    if (i < n) atomicAdd(&cnt[batch[i]], 1.f);
}

__global__ void head_kernel(const float* __restrict__ pool,
                            const float* __restrict__ cnt,
                            const float* __restrict__ d1w,
                            const float* __restrict__ d1b,
                            const float* __restrict__ gma,
                            const float* __restrict__ bta,
                            const float* __restrict__ mean,
                            const float* __restrict__ var,
                            const float* __restrict__ d2w,
                            const float* __restrict__ d2b,
                            float* __restrict__ out)
{
    int g = blockIdx.x;
    int j = threadIdx.x;
    float c = fmaxf(cnt[g], 1.f);
    float inv = 1.f / c;
    float acc = d1b[j];
    for (int k = 0; k < F2; k++)
        acc += (pool[g * F2 + k] * inv) * d1w[k * 64 + j];
    acc = (acc - mean[j]) * rsqrtf(var[j] + 1e-5f) * gma[j] + bta[j];
    acc = (acc >= 0.f) ? acc : 0.1f * acc;
    float v = acc * d2w[j];
    __shared__ float red[64];
    red[j] = v;
    __syncthreads();
    for (int s = 32; s > 0; s >>= 1) {
        if (j < s) red[j] += red[j + s];
        __syncthreads();
    }
    if (j == 0) out[g] = red[0] + d2b[0];
}

// ---------------------------------------------------------------------------
// Host orchestration
// ---------------------------------------------------------------------------
static inline int cdiv(long a, int b) { return (int)((a + b - 1) / b); }

static void run_layer(const float* X, int inF, int F, int D,
                      const float* projW, const float* projB,
                      const float* as0, const float* ad0,
                      const float* as1, const float* ad1,
                      const float* klinW, const float* klinB, const float* q,
                      const int* ei0, const int* ei1,
                      float* h, float* out0, float* out1, float* comb,
                      float* s, float* d, float* amax, float* den,
                      float* alpha, float* wsum, float* attn)
{
    const int n = NNODES, E = NEDGES;
    const long nF = (long)n * F;

    fillk<<<cdiv(2 * F, 256), 256>>>(wsum, 0.f, 2 * F);

    // projection GEMM (tf32 tensor cores)
    {
        dim3 grid(F / GBN, cdiv(n, GBM));
        mma_gemm<<<grid, 256>>>(X, projW, projB, h, n, inF, F, 0, 0, nullptr);
    }

    const float* as_[2] = {as0, as1};
    const float* ad_[2] = {ad0, ad1};
    const int*   ei_[2] = {ei0, ei1};
    float*       outp[2] = {out0, out1};

    for (int r = 0; r < 2; r++) {
        node_scores_kernel<<<cdiv((long)n * NHEAD, 256), 256>>>(
            h, as_[r], ad_[r], s, d, n, F, D);
        fillk<<<cdiv((long)n * NHEAD, 256), 256>>>(amax, -INFINITY, (long)n * NHEAD);
        fillk<<<cdiv((long)n * NHEAD, 256), 256>>>(den, 0.f, (long)n * NHEAD);
        fillk<<<cdiv(nF, 256), 256>>>(outp[r], 0.f, nF);
        edge_alpha_kernel<<<cdiv((long)E * NHEAD, 256), 256>>>(
            ei_[r], s, d, alpha, amax, E);
        edge_exp_kernel<<<cdiv((long)E * NHEAD, 256), 256>>>(
            ei_[r], alpha, amax, den, E);
        scatter_kernel<<<E, F>>>(ei_[r], h, alpha, den, outp[r], E, F, D);
        // semantic GEMM: colsum of tanh(relu(out_r) @ klin + b)  (relu fused)
        dim3 grid(F / GBN, cdiv(n, GBM));
        mma_gemm<<<grid, 256>>>(outp[r], klinW, klinB, nullptr,
                                n, F, F, 1, 1, wsum + r * F);
    }

    semantic_kernel<<<1, 256>>>(wsum, q, attn, F, 1.f / n);
    combine_kernel<<<cdiv(nF, 256), 256>>>(out0, out1, attn, comb, nF);
}

extern "C" void kernel_launch(void* const* d_in, const int* in_sizes, int n_in,
                              void* d_out, int out_size)
{
    const float* x       = (const float*)d_in[0];
    const int*   ei0     = (const int*)d_in[1];
    const int*   ei1     = (const int*)d_in[2];
    const int*   batch   = (const int*)d_in[3];
    const float* proj1_w = (const float*)d_in[4];
    const float* proj1_b = (const float*)d_in[5];
    const float* as1_r0  = (const float*)d_in[6];
    const float* ad1_r0  = (const float*)d_in[7];
    const float* as1_r1  = (const float*)d_in[8];
    const float* ad1_r1  = (const float*)d_in[9];
    const float* klin1_w = (const float*)d_in[10];
    const float* klin1_b = (const float*)d_in[11];
    const float* q1      = (const float*)d_in[12];
    const float* proj2_w = (const float*)d_in[13];
    const float* proj2_b = (const float*)d_in[14];
    const float* as2_r0  = (const float*)d_in[15];
    const float* ad2_r0  = (const float*)d_in[16];
    const float* as2_r1  = (const float*)d_in[17];
    const float* ad2_r1  = (const float*)d_in[18];
    const float* klin2_w = (const float*)d_in[19];
    const float* klin2_b = (const float*)d_in[20];
    const float* q2      = (const float*)d_in[21];
    const float* d1_w    = (const float*)d_in[22];
    const float* d1_b    = (const float*)d_in[23];
    const float* bn_g    = (const float*)d_in[24];
    const float* bn_b    = (const float*)d_in[25];
    const float* bn_m    = (const float*)d_in[26];
    const float* bn_v    = (const float*)d_in[27];
    const float* d2_w    = (const float*)d_in[28];
    const float* d2_b    = (const float*)d_in[29];
    float* out = (float*)d_out;

    float *h, *o0, *o1, *c1, *c2, *s, *d, *amax, *den, *alpha, *wsum, *attn,
          *pool, *cnt;
    cudaGetSymbolAddress((void**)&h,     g_h);
    cudaGetSymbolAddress((void**)&o0,    g_out0);
    cudaGetSymbolAddress((void**)&o1,    g_out1);
    cudaGetSymbolAddress((void**)&c1,    g_comb1);
    cudaGetSymbolAddress((void**)&c2,    g_comb2);
    cudaGetSymbolAddress((void**)&s,     g_s);
    cudaGetSymbolAddress((void**)&d,     g_dd);
    cudaGetSymbolAddress((void**)&amax,  g_amax);
    cudaGetSymbolAddress((void**)&den,   g_den);
    cudaGetSymbolAddress((void**)&alpha, g_alpha);
    cudaGetSymbolAddress((void**)&wsum,  g_wsum);
    cudaGetSymbolAddress((void**)&attn,  g_attn);
    cudaGetSymbolAddress((void**)&pool,  g_pool);
    cudaGetSymbolAddress((void**)&cnt,   g_cnt);

    // Layer 1: 128 -> 256 (H=4, D=64)
    run_layer(x, 128, F1, 64,
              proj1_w, proj1_b, as1_r0, ad1_r0, as1_r1, ad1_r1,
              klin1_w, klin1_b, q1, ei0, ei1,
              h, o0, o1, c1, s, d, amax, den, alpha, wsum, attn);

    // Layer 2: 256 -> 128 (H=4, D=32)
    run_layer(c1, F1, F2, 32,
              proj2_w, proj2_b, as2_r0, ad2_r0, as2_r1, ad2_r1,
              klin2_w, klin2_b, q2, ei0, ei1,
              h, o0, o1, c2, s, d, amax, den, alpha, wsum, attn);

    // Global mean pool + MLP head
    fillk<<<cdiv(NGRAPH * F2, 256), 256>>>(pool, 0.f, NGRAPH * F2);
    fillk<<<1, 64>>>(cnt, 0.f, NGRAPH);
    pool_kernel<<<cdiv((long)NNODES * F2, 256), 256>>>(c2, batch, pool, NNODES, F2);
    count_kernel<<<cdiv(NNODES, 256), 256>>>(batch, cnt, NNODES);
    head_kernel<<<NGRAPH, 64>>>(pool, cnt, d1_w, d1_b, bn_g, bn_b, bn_m, bn_v,
                                d2_w, d2_b, out);
}

// round 4
// speedup vs baseline: 2.7207x; 1.8934x over previous
#include <cuda_runtime.h>
#include <cuda_bf16.h>
#include <math.h>

// Problem constants (match reference)
#define NNODES 50000
#define NEDGES 400000
#define NGRAPH 64
#define NHEAD  4
#define F1 256
#define F2 128
#define NB 196   // ceil(NNODES/256)

// ---------------------------------------------------------------------------
// Device scratch
// ---------------------------------------------------------------------------
__device__ float g_h[NNODES * F1];
__device__ float g_out0[NNODES * F1];
__device__ float g_out1[NNODES * F1];
__device__ float g_s[NNODES * NHEAD];
__device__ float g_dd[NNODES * NHEAD];
__device__ float g_wsum[2 * F1];
__device__ float g_attn[2];
__device__ float g_pool[NGRAPH * F2];
__device__ float g_cnt[NGRAPH];
// CSR (by dst), 2 relations
__device__ int g_deg[2 * NNODES];
__device__ int g_rowptr[2 * NNODES];
__device__ int g_cursor[2 * NNODES];
__device__ int g_eid[2 * NEDGES];
__device__ int g_partials[2 * NB];

// ---------------------------------------------------------------------------
// Helpers
// ---------------------------------------------------------------------------
__device__ __forceinline__ unsigned to_tf32_bits(float x) {
    unsigned r;
    asm("cvt.rna.tf32.f32 %0, %1;" : "=r"(r) : "f"(x));
    return r;
}
__device__ __forceinline__ float to_tf32(float x) {
    return __uint_as_float(to_tf32_bits(x));
}

__device__ __forceinline__ void mma_tf32(float c[4],
                                         const unsigned a[4],
                                         const unsigned b[2]) {
    asm volatile(
        "mma.sync.aligned.m16n8k8.row.col.f32.tf32.tf32.f32 "
        "{%0,%1,%2,%3}, {%4,%5,%6,%7}, {%8,%9}, {%0,%1,%2,%3};"
        : "+f"(c[0]), "+f"(c[1]), "+f"(c[2]), "+f"(c[3])
        : "r"(a[0]), "r"(a[1]), "r"(a[2]), "r"(a[3]),
          "r"(b[0]), "r"(b[1]));
}

__global__ void fillk(float* __restrict__ p, float v, long n) {
    long i = (long)blockIdx.x * blockDim.x + threadIdx.x;
    if (i < n) p[i] = v;
}

// ---------------------------------------------------------------------------
// CSR build kernels
// ---------------------------------------------------------------------------
__global__ void prep_zero(int* __restrict__ deg, float* __restrict__ pool,
                          float* __restrict__ cnt) {
    int i = blockIdx.x * 256 + threadIdx.x;
    if (i < 2 * NNODES) deg[i] = 0;
    if (i < NGRAPH * F2) pool[i] = 0.f;
    if (i < NGRAPH) cnt[i] = 0.f;
}

__global__ void hist_kernel(const int* __restrict__ ei0,
                            const int* __restrict__ ei1,
                            int* __restrict__ deg) {
    int r = blockIdx.y;
    const int* dst = (r == 0 ? ei0 : ei1) + NEDGES;
    int e = blockIdx.x * 256 + threadIdx.x;
    if (e < NEDGES) atomicAdd(&deg[r * NNODES + dst[e]], 1);
}

__global__ void scan1_kernel(const int* __restrict__ deg,
                             int* __restrict__ rowptr,
                             int* __restrict__ partials) {
    int r = blockIdx.y, b = blockIdx.x, t = threadIdx.x;
    int i = b * 256 + t;
    __shared__ int sh[256];
    int v = (i < NNODES) ? deg[r * NNODES + i] : 0;
    sh[t] = v;
    __syncthreads();
    for (int off = 1; off < 256; off <<= 1) {
        int x = (t >= off) ? sh[t - off] : 0;
        __syncthreads();
        sh[t] += x;
        __syncthreads();
    }
    if (i < NNODES) rowptr[r * NNODES + i] = sh[t] - v;  // exclusive
    if (t == 255) partials[r * NB + b] = sh[t];
}

__global__ void scan2_kernel(int* __restrict__ partials) {
    int r = threadIdx.x;
    if (r < 2) {
        int off = 0;
        for (int b = 0; b < NB; b++) {
            int t = partials[r * NB + b];
            partials[r * NB + b] = off;
            off += t;
        }
    }
}

__global__ void scan3_kernel(int* __restrict__ rowptr,
                             const int* __restrict__ partials,
                             int* __restrict__ cursor) {
    int r = blockIdx.y;
    int i = blockIdx.x * 256 + threadIdx.x;
    if (i < NNODES) {
        int v = rowptr[r * NNODES + i] + partials[r * NB + blockIdx.x];
        rowptr[r * NNODES + i] = v;
        cursor[r * NNODES + i] = v;
    }
}

__global__ void fillpos_kernel(const int* __restrict__ ei0,
                               const int* __restrict__ ei1,
                               int* __restrict__ cursor,
                               int* __restrict__ eid) {
    int r = blockIdx.y;
    const int* dst = (r == 0 ? ei0 : ei1) + NEDGES;
    int e = blockIdx.x * 256 + threadIdx.x;
    if (e < NEDGES) {
        int pos = atomicAdd(&cursor[r * NNODES + dst[e]], 1);
        eid[r * NEDGES + pos] = e;
    }
}

// ---------------------------------------------------------------------------
// TF32 tensor-core GEMM: C[M,F] = A[M,K] @ W[K,F] (+bias)
// mode 0: write C = acc + bias
// mode 1: colsum[f] += sum_m tanh(acc + bias[f])
// A-path options: relu_in (relu on A), or A2+attnp (attn-combine of relu(A),relu(A2))
// ---------------------------------------------------------------------------
#define GBM 128
#define GBN 128
#define GBK 16
#define A_STRIDE 20
#define B_STRIDE 136

__device__ __forceinline__ float4 ld_a4(const float* __restrict__ A,
                                        const float* __restrict__ A2,
                                        size_t off, int relu_in, int use2,
                                        float at0, float at1) {
    float4 v = *reinterpret_cast<const float4*>(A + off);
    if (use2) {
        float4 u = *reinterpret_cast<const float4*>(A2 + off);
        v.x = at0 * fmaxf(v.x, 0.f) + at1 * fmaxf(u.x, 0.f);
        v.y = at0 * fmaxf(v.y, 0.f) + at1 * fmaxf(u.y, 0.f);
        v.z = at0 * fmaxf(v.z, 0.f) + at1 * fmaxf(u.z, 0.f);
        v.w = at0 * fmaxf(v.w, 0.f) + at1 * fmaxf(u.w, 0.f);
    } else if (relu_in) {
        v.x = fmaxf(v.x, 0.f); v.y = fmaxf(v.y, 0.f);
        v.z = fmaxf(v.z, 0.f); v.w = fmaxf(v.w, 0.f);
    }
    return v;
}

__global__ __launch_bounds__(256) void mma_gemm(
    const float* __restrict__ A, const float* __restrict__ A2,
    const float* __restrict__ attnp,
    const float* __restrict__ W,
    const float* __restrict__ bias, float* __restrict__ C,
    int M, int K, int F, int mode, int relu_in, float* __restrict__ colsum)
{
    __shared__ float As[2][GBM][A_STRIDE];
    __shared__ float Bs[2][GBK][B_STRIDE];

    const int tid  = threadIdx.x;
    const int lane = tid & 31;
    const int warp = tid >> 5;
    const int wm   = warp & 1;
    const int wn   = warp >> 1;
    const int gid  = lane >> 2;
    const int tig  = lane & 3;

    const int rowBase = blockIdx.y * GBM;
    const int colBase = blockIdx.x * GBN;

    const int use2 = (A2 != nullptr);
    float at0 = 0.f, at1 = 0.f;
    if (use2) { at0 = attnp[0]; at1 = attnp[1]; }

    float acc[4][4][4];
#pragma unroll
    for (int mt = 0; mt < 4; mt++)
#pragma unroll
        for (int nt = 0; nt < 4; nt++)
#pragma unroll
            for (int i = 0; i < 4; i++) acc[mt][nt][i] = 0.f;

    const int a_r0 = tid >> 2;
    const int a_c0 = (tid & 3) * 4;
    const int b_k0 = tid >> 5;
    const int b_c0 = (tid & 31) * 4;

    const int KT = K / GBK;
    float4 ra[2], rb[2];

    {
#pragma unroll
        for (int i = 0; i < 2; i++) {
            int gr = rowBase + a_r0 + i * 64;
            ra[i] = (gr < M) ? ld_a4(A, A2, (size_t)gr * K + a_c0, relu_in, use2, at0, at1)
                             : make_float4(0.f, 0.f, 0.f, 0.f);
            int kr = b_k0 + i * 8;
            rb[i] = *reinterpret_cast<const float4*>(&W[(size_t)kr * F + colBase + b_c0]);
        }
#pragma unroll
        for (int i = 0; i < 2; i++) {
            float4 v;
            v.x = to_tf32(ra[i].x); v.y = to_tf32(ra[i].y);
            v.z = to_tf32(ra[i].z); v.w = to_tf32(ra[i].w);
            *reinterpret_cast<float4*>(&As[0][a_r0 + i * 64][a_c0]) = v;
            float4 w;
            w.x = to_tf32(rb[i].x); w.y = to_tf32(rb[i].y);
            w.z = to_tf32(rb[i].z); w.w = to_tf32(rb[i].w);
            *reinterpret_cast<float4*>(&Bs[0][b_k0 + i * 8][b_c0]) = w;
        }
    }
    __syncthreads();

    for (int kt = 0; kt < KT; kt++) {
        const int buf = kt & 1;
        if (kt + 1 < KT) {
            const int k0 = (kt + 1) * GBK;
#pragma unroll
            for (int i = 0; i < 2; i++) {
                int gr = rowBase + a_r0 + i * 64;
                ra[i] = (gr < M) ? ld_a4(A, A2, (size_t)gr * K + k0 + a_c0, relu_in, use2, at0, at1)
                                 : make_float4(0.f, 0.f, 0.f, 0.f);
                int kr = b_k0 + i * 8;
                rb[i] = *reinterpret_cast<const float4*>(&W[(size_t)(k0 + kr) * F + colBase + b_c0]);
            }
        }
#pragma unroll
        for (int ks = 0; ks < 2; ks++) {
            const int kb = ks * 8;
            unsigned afr[4][4], bfr[4][2];
#pragma unroll
            for (int mt = 0; mt < 4; mt++) {
                int r = wm * 64 + mt * 16 + gid;
                afr[mt][0] = __float_as_uint(As[buf][r][kb + tig]);
                afr[mt][1] = __float_as_uint(As[buf][r + 8][kb + tig]);
                afr[mt][2] = __float_as_uint(As[buf][r][kb + tig + 4]);
                afr[mt][3] = __float_as_uint(As[buf][r + 8][kb + tig + 4]);
            }
#pragma unroll
            for (int nt = 0; nt < 4; nt++) {
                int c = wn * 32 + nt * 8 + gid;
                bfr[nt][0] = __float_as_uint(Bs[buf][kb + tig][c]);
                bfr[nt][1] = __float_as_uint(Bs[buf][kb + tig + 4][c]);
            }
#pragma unroll
            for (int mt = 0; mt < 4; mt++)
#pragma unroll
                for (int nt = 0; nt < 4; nt++)
                    mma_tf32(acc[mt][nt], afr[mt], bfr[nt]);
        }
        if (kt + 1 < KT) {
            const int nbuf = (kt + 1) & 1;
#pragma unroll
            for (int i = 0; i < 2; i++) {
                float4 v;
                v.x = to_tf32(ra[i].x); v.y = to_tf32(ra[i].y);
                v.z = to_tf32(ra[i].z); v.w = to_tf32(ra[i].w);
                *reinterpret_cast<float4*>(&As[nbuf][a_r0 + i * 64][a_c0]) = v;
                float4 w;
                w.x = to_tf32(rb[i].x); w.y = to_tf32(rb[i].y);
                w.z = to_tf32(rb[i].z); w.w = to_tf32(rb[i].w);
                *reinterpret_cast<float4*>(&Bs[nbuf][b_k0 + i * 8][b_c0]) = w;
            }
            __syncthreads();
        }
    }

    if (mode == 0) {
#pragma unroll
        for (int mt = 0; mt < 4; mt++) {
            int r0 = rowBase + wm * 64 + mt * 16 + gid;
            int r1 = r0 + 8;
#pragma unroll
            for (int nt = 0; nt < 4; nt++) {
                int gc = colBase + wn * 32 + nt * 8 + tig * 2;
                float b0 = bias[gc], b1 = bias[gc + 1];
                if (r0 < M) {
                    float2 v = make_float2(acc[mt][nt][0] + b0, acc[mt][nt][1] + b1);
                    *reinterpret_cast<float2*>(&C[(size_t)r0 * F + gc]) = v;
                }
                if (r1 < M) {
                    float2 v = make_float2(acc[mt][nt][2] + b0, acc[mt][nt][3] + b1);
                    *reinterpret_cast<float2*>(&C[(size_t)r1 * F + gc]) = v;
                }
            }
        }
    } else {
#pragma unroll
        for (int nt = 0; nt < 4; nt++) {
            int gc = colBase + wn * 32 + nt * 8 + tig * 2;
            float b0 = bias[gc], b1 = bias[gc + 1];
            float csA = 0.f, csB = 0.f;
#pragma unroll
            for (int mt = 0; mt < 4; mt++) {
                int r0 = rowBase + wm * 64 + mt * 16 + gid;
                int r1 = r0 + 8;
                if (r0 < M) {
                    csA += tanhf(acc[mt][nt][0] + b0);
                    csB += tanhf(acc[mt][nt][1] + b1);
                }
                if (r1 < M) {
                    csA += tanhf(acc[mt][nt][2] + b0);
                    csB += tanhf(acc[mt][nt][3] + b1);
                }
            }
            atomicAdd(&colsum[gc], csA);
            atomicAdd(&colsum[gc + 1], csB);
        }
    }
}

// ---------------------------------------------------------------------------
// Per-(node,head) attention scores
// ---------------------------------------------------------------------------
__global__ void node_scores_kernel(const float* __restrict__ h,
                                   const float* __restrict__ asrc,
                                   const float* __restrict__ adst,
                                   float* __restrict__ s, float* __restrict__ d,
                                   int n, int F, int D)
{
    int idx = blockIdx.x * blockDim.x + threadIdx.x;
    if (idx >= n * NHEAD) return;
    int node = idx / NHEAD;
    int hh   = idx % NHEAD;
    const float* hp = h + (size_t)node * F + hh * D;
    const float* ap = asrc + hh * D;
    const float* bp = adst + hh * D;
    float ss = 0.f, dd = 0.f;
    for (int i = 0; i < D; i++) {
        float v = hp[i];
        ss += v * ap[i];
        dd += v * bp[i];
    }
    s[idx] = ss;
    d[idx] = dd;
}

// ---------------------------------------------------------------------------
// Gather-aggregate: one warp per dst node; softmax + weighted sum, no atomics
// ---------------------------------------------------------------------------
template<int F, int D>
__global__ __launch_bounds__(256) void agg_kernel(
    const int* __restrict__ rowptr, const int* __restrict__ deg,
    const int* __restrict__ eid, const int* __restrict__ esrc,
    const float* __restrict__ h, const float* __restrict__ s,
    const float* __restrict__ dvals, float* __restrict__ out, int n)
{
    int w = blockIdx.x * (blockDim.x >> 5) + (threadIdx.x >> 5);
    int lane = threadIdx.x & 31;
    if (w >= n) return;
    const int dg = deg[w];
    const int st = rowptr[w];
    constexpr int C = F / 32;
    float acc[C];
#pragma unroll
    for (int c = 0; c < C; c++) acc[c] = 0.f;
    float dd[4];
#pragma unroll
    for (int t = 0; t < 4; t++) dd[t] = dvals[w * 4 + t];

    // pass 1: per-head max over in-edges
    float m[4] = {-1e30f, -1e30f, -1e30f, -1e30f};
    for (int j = lane; j < dg; j += 32) {
        int e = eid[st + j];
        int sr = esrc[e];
#pragma unroll
        for (int t = 0; t < 4; t++) {
            float v = s[sr * 4 + t] + dd[t];
            v = (v >= 0.f) ? v : 0.2f * v;
            m[t] = fmaxf(m[t], v);
        }
    }
#pragma unroll
    for (int o = 16; o > 0; o >>= 1)
#pragma unroll
        for (int t = 0; t < 4; t++)
            m[t] = fmaxf(m[t], __shfl_xor_sync(0xffffffffu, m[t], o));

    // pass 2: serial edges, accumulate unnormalized sums
    float sums[4] = {0.f, 0.f, 0.f, 0.f};
    for (int j = 0; j < dg; j++) {
        int e = eid[st + j];
        int sr = esrc[e];
        float p[4];
#pragma unroll
        for (int t = 0; t < 4; t++) {
            float v = s[sr * 4 + t] + dd[t];
            v = (v >= 0.f) ? v : 0.2f * v;
            p[t] = expf(v - m[t]);
            sums[t] += p[t];
        }
        const float* hr = h + (size_t)sr * F;
#pragma unroll
        for (int c = 0; c < C; c++) {
            int f = lane + 32 * c;
            acc[c] += hr[f] * p[f / D];
        }
    }
#pragma unroll
    for (int c = 0; c < C; c++) {
        int f = lane + 32 * c;
        out[(size_t)w * F + f] = acc[c] / (sums[f / D] + 1e-16f);
    }
}

// ---------------------------------------------------------------------------
// Semantic attention
// ---------------------------------------------------------------------------
__global__ void semantic_kernel(const float* __restrict__ wsum,
                                const float* __restrict__ q,
                                float* __restrict__ attn, int F, float invN)
{
    __shared__ float sh0[256], sh1[256];
    int t = threadIdx.x;
    float p0 = 0.f, p1 = 0.f;
    for (int f = t; f < F; f += 256) {
        float qf = q[f];
        p0 += wsum[f] * invN * qf;
        p1 += wsum[F + f] * invN * qf;
    }
    sh0[t] = p0; sh1[t] = p1;
    __syncthreads();
    for (int s = 128; s > 0; s >>= 1) {
        if (t < s) { sh0[t] += sh0[t + s]; sh1[t] += sh1[t + s]; }
        __syncthreads();
    }
    if (t == 0) {
        float m  = fmaxf(sh0[0], sh1[0]);
        float e0 = expf(sh0[0] - m);
        float e1 = expf(sh1[0] - m);
        float inv = 1.f / (e0 + e1);
        attn[0] = e0 * inv;
        attn[1] = e1 * inv;
    }
}

// ---------------------------------------------------------------------------
// Final combine + pool (fused), count, head
// ---------------------------------------------------------------------------
__global__ void combine_pool_kernel(const float* __restrict__ o0,
                                    const float* __restrict__ o1,
                                    const float* __restrict__ attn,
                                    const int* __restrict__ batch,
                                    float* __restrict__ pool, int n, int F)
{
    long i = (long)blockIdx.x * blockDim.x + threadIdx.x;
    if (i >= (long)n * F) return;
    int node = (int)(i / F);
    int f    = (int)(i % F);
    float v = attn[0] * fmaxf(o0[i], 0.f) + attn[1] * fmaxf(o1[i], 0.f);
    atomicAdd(&pool[batch[node] * F + f], v);
}

__global__ void count_kernel(const int* __restrict__ batch,
                             float* __restrict__ cnt, int n)
{
    int i = blockIdx.x * blockDim.x + threadIdx.x;
    if (i < n) atomicAdd(&cnt[batch[i]], 1.f);
}

__global__ void head_kernel(const float* __restrict__ pool,
                            const float* __restrict__ cnt,
                            const float* __restrict__ d1w,
                            const float* __restrict__ d1b,
                            const float* __restrict__ gma,
                            const float* __restrict__ bta,
                            const float* __restrict__ mean,
                            const float* __restrict__ var,
                            const float* __restrict__ d2w,
                            const float* __restrict__ d2b,
                            float* __restrict__ out)
{
    int g = blockIdx.x;
    int j = threadIdx.x;
    float c = fmaxf(cnt[g], 1.f);
    float inv = 1.f / c;
    float acc = d1b[j];
    for (int k = 0; k < F2; k++)
        acc += (pool[g * F2 + k] * inv) * d1w[k * 64 + j];
    acc = (acc - mean[j]) * rsqrtf(var[j] + 1e-5f) * gma[j] + bta[j];
    acc = (acc >= 0.f) ? acc : 0.1f * acc;
    float v = acc * d2w[j];
    __shared__ float red[64];
    red[j] = v;
    __syncthreads();
    for (int s = 32; s > 0; s >>= 1) {
        if (j < s) red[j] += red[j + s];
        __syncthreads();
    }
    if (j == 0) out[g] = red[0] + d2b[0];
}

// ---------------------------------------------------------------------------
// Host orchestration
// ---------------------------------------------------------------------------
static inline int cdiv(long a, int b) { return (int)((a + b - 1) / b); }

extern "C" void kernel_launch(void* const* d_in, const int* in_sizes, int n_in,
                              void* d_out, int out_size)
{
    const float* x       = (const float*)d_in[0];
    const int*   ei0     = (const int*)d_in[1];
    const int*   ei1     = (const int*)d_in[2];
    const int*   batch   = (const int*)d_in[3];
    const float* proj1_w = (const float*)d_in[4];
    const float* proj1_b = (const float*)d_in[5];
    const float* as1_r0  = (const float*)d_in[6];
    const float* ad1_r0  = (const float*)d_in[7];
    const float* as1_r1  = (const float*)d_in[8];
    const float* ad1_r1  = (const float*)d_in[9];
    const float* klin1_w = (const float*)d_in[10];
    const float* klin1_b = (const float*)d_in[11];
    const float* q1      = (const float*)d_in[12];
    const float* proj2_w = (const float*)d_in[13];
    const float* proj2_b = (const float*)d_in[14];
    const float* as2_r0  = (const float*)d_in[15];
    const float* ad2_r0  = (const float*)d_in[16];
    const float* as2_r1  = (const float*)d_in[17];
    const float* ad2_r1  = (const float*)d_in[18];
    const float* klin2_w = (const float*)d_in[19];
    const float* klin2_b = (const float*)d_in[20];
    const float* q2      = (const float*)d_in[21];
    const float* d1_w    = (const float*)d_in[22];
    const float* d1_b    = (const float*)d_in[23];
    const float* bn_g    = (const float*)d_in[24];
    const float* bn_b    = (const float*)d_in[25];
    const float* bn_m    = (const float*)d_in[26];
    const float* bn_v    = (const float*)d_in[27];
    const float* d2_w    = (const float*)d_in[28];
    const float* d2_b    = (const float*)d_in[29];
    float* out = (float*)d_out;

    float *h, *o0, *o1, *s, *d, *wsum, *attn, *pool, *cnt;
    int *deg, *rowptr, *cursor, *eid, *partials;
    cudaGetSymbolAddress((void**)&h,       g_h);
    cudaGetSymbolAddress((void**)&o0,      g_out0);
    cudaGetSymbolAddress((void**)&o1,      g_out1);
    cudaGetSymbolAddress((void**)&s,       g_s);
    cudaGetSymbolAddress((void**)&d,       g_dd);
    cudaGetSymbolAddress((void**)&wsum,    g_wsum);
    cudaGetSymbolAddress((void**)&attn,    g_attn);
    cudaGetSymbolAddress((void**)&pool,    g_pool);
    cudaGetSymbolAddress((void**)&cnt,     g_cnt);
    cudaGetSymbolAddress((void**)&deg,     g_deg);
    cudaGetSymbolAddress((void**)&rowptr,  g_rowptr);
    cudaGetSymbolAddress((void**)&cursor,  g_cursor);
    cudaGetSymbolAddress((void**)&eid,     g_eid);
    cudaGetSymbolAddress((void**)&partials,g_partials);

    const int n = NNODES, E = NEDGES;
    const int egrid = cdiv(E, 256);
    const int agg_blocks = cdiv(n, 8);   // 8 warps/block, warp per node

    // ---- CSR build (launches 1-5), proj1 GEMM at launch 6 (ncu capture) ----
    prep_zero<<<cdiv(2 * n, 256), 256>>>(deg, pool, cnt);
    hist_kernel<<<dim3(egrid, 2), 256>>>(ei0, ei1, deg);
    scan1_kernel<<<dim3(NB, 2), 256>>>(deg, rowptr, partials);
    scan2_kernel<<<1, 32>>>(partials);
    scan3_kernel<<<dim3(NB, 2), 256>>>(rowptr, partials, cursor);
    {   // launch #6: proj1 GEMM (independent of CSR)
        dim3 grid(F1 / GBN, cdiv(n, GBM));
        mma_gemm<<<grid, 256>>>(x, nullptr, nullptr, proj1_w, proj1_b, h,
                                n, 128, F1, 0, 0, nullptr);
    }
    fillpos_kernel<<<dim3(egrid, 2), 256>>>(ei0, ei1, cursor, eid);

    const int* esrc_[2] = {ei0, ei1};

    // ---- Layer 1 (F=256, D=64) ----
    fillk<<<cdiv(2 * F1, 256), 256>>>(wsum, 0.f, 2 * F1);
    {
        const float* as_[2] = {as1_r0, as1_r1};
        const float* ad_[2] = {ad1_r0, ad1_r1};
        float* outp[2] = {o0, o1};
        for (int r = 0; r < 2; r++) {
            node_scores_kernel<<<cdiv(n * NHEAD, 256), 256>>>(
                h, as_[r], ad_[r], s, d, n, F1, 64);
            agg_kernel<F1, 64><<<agg_blocks, 256>>>(
                rowptr + r * n, deg + r * n, eid + r * E, esrc_[r],
                h, s, d, outp[r], n);
            dim3 grid(F1 / GBN, cdiv(n, GBM));
            mma_gemm<<<grid, 256>>>(outp[r], nullptr, nullptr, klin1_w, klin1_b,
                                    nullptr, n, F1, F1, 1, 1, wsum + r * F1);
        }
    }
    semantic_kernel<<<1, 256>>>(wsum, q1, attn, F1, 1.f / n);

    // ---- Layer 2 (F=128, D=32); proj2 fuses attn-combine of layer-1 outs ----
    fillk<<<cdiv(2 * F2, 256), 256>>>(wsum, 0.f, 2 * F2);
    {
        dim3 grid(F2 / GBN, cdiv(n, GBM));
        mma_gemm<<<grid, 256>>>(o0, o1, attn, proj2_w, proj2_b, h,
                                n, F1, F2, 0, 0, nullptr);
    }
    {
        const float* as_[2] = {as2_r0, as2_r1};
        const float* ad_[2] = {ad2_r0, ad2_r1};
        float* outp[2] = {o0, o1};
        for (int r = 0; r < 2; r++) {
            node_scores_kernel<<<cdiv(n * NHEAD, 256), 256>>>(
                h, as_[r], ad_[r], s, d, n, F2, 32);
            agg_kernel<F2, 32><<<agg_blocks, 256>>>(
                rowptr + r * n, deg + r * n, eid + r * E, esrc_[r],
                h, s, d, outp[r], n);
            dim3 grid(F2 / GBN, cdiv(n, GBM));
            mma_gemm<<<grid, 256>>>(outp[r], nullptr, nullptr, klin2_w, klin2_b,
                                    nullptr, n, F2, F2, 1, 1, wsum + r * F2);
        }
    }
    semantic_kernel<<<1, 256>>>(wsum, q2, attn, F2, 1.f / n);

    // ---- Combine+pool (fused), count, head ----
    combine_pool_kernel<<<cdiv((long)n * F2, 256), 256>>>(
        o0, o1, attn, batch, pool, n, F2);
    count_kernel<<<cdiv(n, 256), 256>>>(batch, cnt, n);
    head_kernel<<<NGRAPH, 64>>>(pool, cnt, d1_w, d1_b, bn_g, bn_b, bn_m, bn_v,
                                d2_w, d2_b, out);
}

// round 6
// speedup vs baseline: 3.0300x; 1.1137x over previous
#include <cuda_runtime.h>
#include <cuda_bf16.h>
#include <cstdint>
#include <math.h>

// Problem constants (match reference)
#define NNODES 50000
#define NEDGES 400000
#define NGRAPH 64
#define NHEAD  4
#define F1 256
#define F2 128
#define NB 196   // ceil(NNODES/256)

// ---------------------------------------------------------------------------
// Device scratch
// ---------------------------------------------------------------------------
__device__ float g_h[NNODES * F1];
__device__ float g_out0[NNODES * F1];
__device__ float g_out1[NNODES * F1];
__device__ float g_x[NNODES * 128];         // tf32-rounded input features
__device__ float g_wa[128 * 256];           // rounded proj1_w
__device__ float g_wb[256 * 256];           // rounded klin1_w
__device__ float g_wc[128 * 128];           // rounded klin2_w
__device__ float g_s[2 * NNODES * NHEAD];
__device__ float g_dd[2 * NNODES * NHEAD];
__device__ float g_wsum[2 * F1];
__device__ float g_attn[2];
__device__ float g_pool[NGRAPH * F2];
__device__ float g_cnt[NGRAPH];
// CSR (by dst), 2 relations
__device__ int g_deg[2 * NNODES];
__device__ int g_rowptr[2 * NNODES];
__device__ int g_cursor[2 * NNODES];
__device__ int g_eid[2 * NEDGES];
__device__ int g_partials[2 * NB];

// ---------------------------------------------------------------------------
// Helpers
// ---------------------------------------------------------------------------
__device__ __forceinline__ unsigned to_tf32_bits(float x) {
    unsigned r;
    asm("cvt.rna.tf32.f32 %0, %1;" : "=r"(r) : "f"(x));
    return r;
}
__device__ __forceinline__ float to_tf32(float x) {
    return __uint_as_float(to_tf32_bits(x));
}

__device__ __forceinline__ void mma_tf32(float c[4],
                                         const unsigned a[4],
                                         const unsigned b[2]) {
    asm volatile(
        "mma.sync.aligned.m16n8k8.row.col.f32.tf32.tf32.f32 "
        "{%0,%1,%2,%3}, {%4,%5,%6,%7}, {%8,%9}, {%0,%1,%2,%3};"
        : "+f"(c[0]), "+f"(c[1]), "+f"(c[2]), "+f"(c[3])
        : "r"(a[0]), "r"(a[1]), "r"(a[2]), "r"(a[3]),
          "r"(b[0]), "r"(b[1]));
}

__device__ __forceinline__ void cp_async16(uint32_t s, const void* g, bool v) {
    int sz = v ? 16 : 0;
    asm volatile("cp.async.ca.shared.global [%0], [%1], 16, %2;"
                 :: "r"(s), "l"(g), "r"(sz));
}
__device__ __forceinline__ void cp_commit() {
    asm volatile("cp.async.commit_group;" ::: "memory");
}
template<int N>
__device__ __forceinline__ void cp_wait() {
    asm volatile("cp.async.wait_group %0;" :: "n"(N) : "memory");
}

__global__ void fillk(float* __restrict__ p, float v, long n) {
    long i = (long)blockIdx.x * blockDim.x + threadIdx.x;
    if (i < n) p[i] = v;
}

__global__ void round_copy(const float* __restrict__ in,
                           float* __restrict__ out, long n) {
    long i = (long)blockIdx.x * blockDim.x + threadIdx.x;
    if (i < n) out[i] = to_tf32(in[i]);
}

// ---------------------------------------------------------------------------
// CSR build kernels
// ---------------------------------------------------------------------------
__global__ void prep_zero(int* __restrict__ deg, float* __restrict__ pool,
                          float* __restrict__ cnt) {
    int i = blockIdx.x * 256 + threadIdx.x;
    if (i < 2 * NNODES) deg[i] = 0;
    if (i < NGRAPH * F2) pool[i] = 0.f;
    if (i < NGRAPH) cnt[i] = 0.f;
}

__global__ void hist_kernel(const int* __restrict__ ei0,
                            const int* __restrict__ ei1,
                            int* __restrict__ deg) {
    int r = blockIdx.y;
    const int* dst = (r == 0 ? ei0 : ei1) + NEDGES;
    int e = blockIdx.x * 256 + threadIdx.x;
    if (e < NEDGES) atomicAdd(&deg[r * NNODES + dst[e]], 1);
}

__global__ void scan1_kernel(const int* __restrict__ deg,
                             int* __restrict__ rowptr,
                             int* __restrict__ partials) {
    int r = blockIdx.y, b = blockIdx.x, t = threadIdx.x;
    int i = b * 256 + t;
    __shared__ int sh[256];
    int v = (i < NNODES) ? deg[r * NNODES + i] : 0;
    sh[t] = v;
    __syncthreads();
    for (int off = 1; off < 256; off <<= 1) {
        int x = (t >= off) ? sh[t - off] : 0;
        __syncthreads();
        sh[t] += x;
        __syncthreads();
    }
    if (i < NNODES) rowptr[r * NNODES + i] = sh[t] - v;  // exclusive
    if (t == 255) partials[r * NB + b] = sh[t];
}

__global__ void scan2_kernel(int* __restrict__ partials) {
    int r = blockIdx.x, t = threadIdx.x;
    __shared__ int sh[256];
    int v = (t < NB) ? partials[r * NB + t] : 0;
    sh[t] = v;
    __syncthreads();
    for (int off = 1; off < 256; off <<= 1) {
        int x = (t >= off) ? sh[t - off] : 0;
        __syncthreads();
        sh[t] += x;
        __syncthreads();
    }
    if (t < NB) partials[r * NB + t] = sh[t] - v;  // exclusive
}

__global__ void scan3_kernel(int* __restrict__ rowptr,
                             const int* __restrict__ partials,
                             int* __restrict__ cursor) {
    int r = blockIdx.y;
    int i = blockIdx.x * 256 + threadIdx.x;
    if (i < NNODES) {
        int v = rowptr[r * NNODES + i] + partials[r * NB + blockIdx.x];
        rowptr[r * NNODES + i] = v;
        cursor[r * NNODES + i] = v;
    }
}

__global__ void fillpos_kernel(const int* __restrict__ ei0,
                               const int* __restrict__ ei1,
                               int* __restrict__ cursor,
                               int* __restrict__ eid) {
    int r = blockIdx.y;
    const int* dst = (r == 0 ? ei0 : ei1) + NEDGES;
    int e = blockIdx.x * 256 + threadIdx.x;
    if (e < NEDGES) {
        int pos = atomicAdd(&cursor[r * NNODES + dst[e]], 1);
        eid[r * NEDGES + pos] = e;
    }
}

// ---------------------------------------------------------------------------
// Fast TF32 GEMM (cp.async 4-stage). A and W MUST be pre-rounded to tf32.
// C[M,F] = A[M,K] @ W[K,F] (+bias)
// mode 0: write C = acc + bias; mode 1: colsum += sum_m tanh(acc + bias)
// grid.z selects A0/A1 (batched klin GEMMs); colsum offset = z*F.
// ---------------------------------------------------------------------------
#define GBM 128
#define GBN 128
#define FBK 8
#define FA_STRIDE 12
#define FB_STRIDE 136
#define FSTAGES 4

__global__ __launch_bounds__(256) void mma_gemm_async(
    const float* __restrict__ A0, const float* __restrict__ A1,
    const float* __restrict__ W,
    const float* __restrict__ bias, float* __restrict__ C,
    int M, int K, int F, int mode, float* __restrict__ colsum)
{
    __shared__ float As[FSTAGES][GBM][FA_STRIDE];   // 4*128*12*4 = 24576 B
    __shared__ float Bs[FSTAGES][FBK][FB_STRIDE];   // 4*8*136*4  = 17408 B

    const float* __restrict__ A = (blockIdx.z == 0) ? A0 : A1;
    float* cs = (mode == 1) ? colsum + blockIdx.z * F : nullptr;

    const int tid  = threadIdx.x;
    const int lane = tid & 31;
    const int warp = tid >> 5;
    const int wm   = warp & 1;
    const int wn   = warp >> 1;
    const int gid  = lane >> 2;
    const int tig  = lane & 3;

    const int rowBase = blockIdx.y * GBM;
    const int colBase = blockIdx.x * GBN;

    const int a_r = tid >> 1;          // 0..127
    const int a_c = (tid & 1) * 4;     // 0 or 4
    const int b_r = tid >> 5;          // 0..7
    const int b_c = (tid & 31) * 4;    // 0..124
    const bool a_valid = (rowBase + a_r) < M;
    const uint32_t a_sbase = (uint32_t)__cvta_generic_to_shared(&As[0][a_r][a_c]);
    const uint32_t b_sbase = (uint32_t)__cvta_generic_to_shared(&Bs[0][b_r][b_c]);
    const size_t a_goff = (size_t)(rowBase + a_r) * K + a_c;
    const size_t b_goff = (size_t)b_r * F + colBase + b_c;
    const uint32_t a_stage_b = GBM * FA_STRIDE * 4;
    const uint32_t b_stage_b = FBK * FB_STRIDE * 4;

    float acc[4][4][4];
#pragma unroll
    for (int mt = 0; mt < 4; mt++)
#pragma unroll
        for (int nt = 0; nt < 4; nt++)
#pragma unroll
            for (int i = 0; i < 4; i++) acc[mt][nt][i] = 0.f;

    const int KT = K / FBK;

#define ISSUE(stage, kt_) do {                                              \
        cp_async16(a_sbase + (stage) * a_stage_b,                           \
                   A + a_goff + (size_t)(kt_) * FBK, a_valid);              \
        cp_async16(b_sbase + (stage) * b_stage_b,                           \
                   W + b_goff + (size_t)(kt_) * FBK * F, true);             \
        cp_commit();                                                        \
    } while (0)

    ISSUE(0, 0);
    ISSUE(1, 1);
    ISSUE(2, 2);

    for (int kt = 0; kt < KT; kt++) {
        const int rem = KT - kt - 1;
        if (rem >= 2)      cp_wait<2>();
        else if (rem == 1) cp_wait<1>();
        else               cp_wait<0>();
        __syncthreads();

        const int buf = kt & (FSTAGES - 1);
        unsigned afr[4][4], bfr[4][2];
#pragma unroll
        for (int mt = 0; mt < 4; mt++) {
            int r = wm * 64 + mt * 16 + gid;
            afr[mt][0] = __float_as_uint(As[buf][r][tig]);
            afr[mt][1] = __float_as_uint(As[buf][r + 8][tig]);
            afr[mt][2] = __float_as_uint(As[buf][r][tig + 4]);
            afr[mt][3] = __float_as_uint(As[buf][r + 8][tig + 4]);
        }
#pragma unroll
        for (int nt = 0; nt < 4; nt++) {
            int c = wn * 32 + nt * 8 + gid;
            bfr[nt][0] = __float_as_uint(Bs[buf][tig][c]);
            bfr[nt][1] = __float_as_uint(Bs[buf][tig + 4][c]);
        }
#pragma unroll
        for (int mt = 0; mt < 4; mt++)
#pragma unroll
            for (int nt = 0; nt < 4; nt++)
                mma_tf32(acc[mt][nt], afr[mt], bfr[nt]);

        if (kt + FSTAGES - 1 < KT)
            ISSUE((kt + FSTAGES - 1) & (FSTAGES - 1), kt + FSTAGES - 1);
    }
#undef ISSUE

    if (mode == 0) {
#pragma unroll
        for (int mt = 0; mt < 4; mt++) {
            int r0 = rowBase + wm * 64 + mt * 16 + gid;
            int r1 = r0 + 8;
#pragma unroll
            for (int nt = 0; nt < 4; nt++) {
                int gc = colBase + wn * 32 + nt * 8 + tig * 2;
                float b0 = bias[gc], b1 = bias[gc + 1];
                if (r0 < M) {
                    float2 v = make_float2(acc[mt][nt][0] + b0, acc[mt][nt][1] + b1);
                    *reinterpret_cast<float2*>(&C[(size_t)r0 * F + gc]) = v;
                }
                if (r1 < M) {
                    float2 v = make_float2(acc[mt][nt][2] + b0, acc[mt][nt][3] + b1);
                    *reinterpret_cast<float2*>(&C[(size_t)r1 * F + gc]) = v;
                }
            }
        }
    } else {
#pragma unroll
        for (int nt = 0; nt < 4; nt++) {
            int gc = colBase + wn * 32 + nt * 8 + tig * 2;
            float b0 = bias[gc], b1 = bias[gc + 1];
            float csA = 0.f, csB = 0.f;
#pragma unroll
            for (int mt = 0; mt < 4; mt++) {
                int r0 = rowBase + wm * 64 + mt * 16 + gid;
                int r1 = r0 + 8;
                if (r0 < M) {
                    csA += tanhf(acc[mt][nt][0] + b0);
                    csB += tanhf(acc[mt][nt][1] + b1);
                }
                if (r1 < M) {
                    csA += tanhf(acc[mt][nt][2] + b0);
                    csB += tanhf(acc[mt][nt][3] + b1);
                }
            }
            atomicAdd(&cs[gc], csA);
            atomicAdd(&cs[gc + 1], csB);
        }
    }
}

// ---------------------------------------------------------------------------
// Register-staging TF32 GEMM, used only for proj2 (fused attn-combine on A).
// A-path: at0*A + at1*A2 (inputs already relu'd), rounded at staging.
// ---------------------------------------------------------------------------
#define GBK 16
#define A_STRIDE 20
#define B_STRIDE 136

__global__ __launch_bounds__(256) void mma_gemm_combine(
    const float* __restrict__ A, const float* __restrict__ A2,
    const float* __restrict__ attnp,
    const float* __restrict__ W,
    const float* __restrict__ bias, float* __restrict__ C,
    int M, int K, int F)
{
    __shared__ float As[2][GBM][A_STRIDE];
    __shared__ float Bs[2][GBK][B_STRIDE];

    const int tid  = threadIdx.x;
    const int lane = tid & 31;
    const int warp = tid >> 5;
    const int wm   = warp & 1;
    const int wn   = warp >> 1;
    const int gid  = lane >> 2;
    const int tig  = lane & 3;

    const int rowBase = blockIdx.y * GBM;
    const int colBase = blockIdx.x * GBN;

    const float at0 = attnp[0], at1 = attnp[1];

    float acc[4][4][4];
#pragma unroll
    for (int mt = 0; mt < 4; mt++)
#pragma unroll
        for (int nt = 0; nt < 4; nt++)
#pragma unroll
            for (int i = 0; i < 4; i++) acc[mt][nt][i] = 0.f;

    const int a_r0 = tid >> 2;
    const int a_c0 = (tid & 3) * 4;
    const int b_k0 = tid >> 5;
    const int b_c0 = (tid & 31) * 4;

    const int KT = K / GBK;
    float4 ra[2], rb[2];

#define LDA(gr, off) ({                                                      \
        float4 v = *reinterpret_cast<const float4*>(A + (off));              \
        float4 u = *reinterpret_cast<const float4*>(A2 + (off));             \
        v.x = at0 * v.x + at1 * u.x;  v.y = at0 * v.y + at1 * u.y;           \
        v.z = at0 * v.z + at1 * u.z;  v.w = at0 * v.w + at1 * u.w;  v; })

    {
#pragma unroll
        for (int i = 0; i < 2; i++) {
            int gr = rowBase + a_r0 + i * 64;
            ra[i] = (gr < M) ? LDA(gr, (size_t)gr * K + a_c0)
                             : make_float4(0.f, 0.f, 0.f, 0.f);
            int kr = b_k0 + i * 8;
            rb[i] = *reinterpret_cast<const float4*>(&W[(size_t)kr * F + colBase + b_c0]);
        }
#pragma unroll
        for (int i = 0; i < 2; i++) {
            float4 v;
            v.x = to_tf32(ra[i].x); v.y = to_tf32(ra[i].y);
            v.z = to_tf32(ra[i].z); v.w = to_tf32(ra[i].w);
            *reinterpret_cast<float4*>(&As[0][a_r0 + i * 64][a_c0]) = v;
            float4 w;
            w.x = to_tf32(rb[i].x); w.y = to_tf32(rb[i].y);
            w.z = to_tf32(rb[i].z); w.w = to_tf32(rb[i].w);
            *reinterpret_cast<float4*>(&Bs[0][b_k0 + i * 8][b_c0]) = w;
        }
    }
    __syncthreads();

    for (int kt = 0; kt < KT; kt++) {
        const int buf = kt & 1;
        if (kt + 1 < KT) {
            const int k0 = (kt + 1) * GBK;
#pragma unroll
            for (int i = 0; i < 2; i++) {
                int gr = rowBase + a_r0 + i * 64;
                ra[i] = (gr < M) ? LDA(gr, (size_t)gr * K + k0 + a_c0)
                                 : make_float4(0.f, 0.f, 0.f, 0.f);
                int kr = b_k0 + i * 8;
                rb[i] = *reinterpret_cast<const float4*>(&W[(size_t)(k0 + kr) * F + colBase + b_c0]);
            }
        }
#pragma unroll
        for (int ks = 0; ks < 2; ks++) {
            const int kb = ks * 8;
            unsigned afr[4][4], bfr[4][2];
#pragma unroll
            for (int mt = 0; mt < 4; mt++) {
                int r = wm * 64 + mt * 16 + gid;
                afr[mt][0] = __float_as_uint(As[buf][r][kb + tig]);
                afr[mt][1] = __float_as_uint(As[buf][r + 8][kb + tig]);
                afr[mt][2] = __float_as_uint(As[buf][r][kb + tig + 4]);
                afr[mt][3] = __float_as_uint(As[buf][r + 8][kb + tig + 4]);
            }
#pragma unroll
            for (int nt = 0; nt < 4; nt++) {
                int c = wn * 32 + nt * 8 + gid;
                bfr[nt][0] = __float_as_uint(Bs[buf][kb + tig][c]);
                bfr[nt][1] = __float_as_uint(Bs[buf][kb + tig + 4][c]);
            }
#pragma unroll
            for (int mt = 0; mt < 4; mt++)
#pragma unroll
                for (int nt = 0; nt < 4; nt++)
                    mma_tf32(acc[mt][nt], afr[mt], bfr[nt]);
        }
        if (kt + 1 < KT) {
            const int nbuf = (kt + 1) & 1;
#pragma unroll
            for (int i = 0; i < 2; i++) {
                float4 v;
                v.x = to_tf32(ra[i].x); v.y = to_tf32(ra[i].y);
                v.z = to_tf32(ra[i].z); v.w = to_tf32(ra[i].w);
                *reinterpret_cast<float4*>(&As[nbuf][a_r0 + i * 64][a_c0]) = v;
                float4 w;
                w.x = to_tf32(rb[i].x); w.y = to_tf32(rb[i].y);
                w.z = to_tf32(rb[i].z); w.w = to_tf32(rb[i].w);
                *reinterpret_cast<float4*>(&Bs[nbuf][b_k0 + i * 8][b_c0]) = w;
            }
            __syncthreads();
        }
    }
#undef LDA

#pragma unroll
    for (int mt = 0; mt < 4; mt++) {
        int r0 = rowBase + wm * 64 + mt * 16 + gid;
        int r1 = r0 + 8;
#pragma unroll
        for (int nt = 0; nt < 4; nt++) {
            int gc = colBase + wn * 32 + nt * 8 + tig * 2;
            float b0 = bias[gc], b1 = bias[gc + 1];
            if (r0 < M) {
                float2 v = make_float2(acc[mt][nt][0] + b0, acc[mt][nt][1] + b1);
                *reinterpret_cast<float2*>(&C[(size_t)r0 * F + gc]) = v;
            }
            if (r1 < M) {
                float2 v = make_float2(acc[mt][nt][2] + b0, acc[mt][nt][3] + b1);
                *reinterpret_cast<float2*>(&C[(size_t)r1 * F + gc]) = v;
            }
        }
    }
}

// ---------------------------------------------------------------------------
// Per-(node,head) attention scores, both relations in one launch (grid.y)
// ---------------------------------------------------------------------------
__global__ void node_scores_kernel(const float* __restrict__ h,
                                   const float* __restrict__ as0,
                                   const float* __restrict__ ad0,
                                   const float* __restrict__ as1,
                                   const float* __restrict__ ad1,
                                   float* __restrict__ s, float* __restrict__ d,
                                   int n, int F, int D)
{
    int r = blockIdx.y;
    const float* asrc = r == 0 ? as0 : as1;
    const float* adst = r == 0 ? ad0 : ad1;
    int idx = blockIdx.x * blockDim.x + threadIdx.x;
    if (idx >= n * NHEAD) return;
    int node = idx / NHEAD;
    int hh   = idx % NHEAD;
    const float* hp = h + (size_t)node * F + hh * D;
    const float* ap = asrc + hh * D;
    const float* bp = adst + hh * D;
    float ss = 0.f, dd = 0.f;
    for (int i = 0; i < D; i++) {
        float v = hp[i];
        ss += v * ap[i];
        dd += v * bp[i];
    }
    s[r * n * NHEAD + idx] = ss;
    d[r * n * NHEAD + idx] = dd;
}

// ---------------------------------------------------------------------------
// Gather-aggregate: warp per dst node, both relations (grid.y).
// Writes tf32(relu(out)) — downstream consumers only use relu(out).
// ---------------------------------------------------------------------------
template<int F, int D>
__global__ __launch_bounds__(256) void agg_kernel(
    const int* __restrict__ rowptr, const int* __restrict__ deg,
    const int* __restrict__ eid,
    const int* __restrict__ esrc0, const int* __restrict__ esrc1,
    const float* __restrict__ h, const float* __restrict__ s,
    const float* __restrict__ dvals,
    float* __restrict__ out0, float* __restrict__ out1, int n)
{
    const int r = blockIdx.y;
    const int* __restrict__ esrc = r == 0 ? esrc0 : esrc1;
    float* __restrict__ out = r == 0 ? out0 : out1;
    const int* rp = rowptr + r * n;
    const int* dgp = deg + r * n;
    const int* eip = eid + r * NEDGES;
    const float* sp = s + (size_t)r * n * NHEAD;
    const float* dp = dvals + (size_t)r * n * NHEAD;

    int w = blockIdx.x * (blockDim.x >> 5) + (threadIdx.x >> 5);
    int lane = threadIdx.x & 31;
    if (w >= n) return;
    const int dg = dgp[w];
    const int st = rp[w];
    constexpr int C = F / 32;
    float acc[C];
#pragma unroll
    for (int c = 0; c < C; c++) acc[c] = 0.f;
    float dd[4];
#pragma unroll
    for (int t = 0; t < 4; t++) dd[t] = dp[w * 4 + t];

    float m[4] = {-1e30f, -1e30f, -1e30f, -1e30f};
    for (int j = lane; j < dg; j += 32) {
        int e = eip[st + j];
        int sr = esrc[e];
#pragma unroll
        for (int t = 0; t < 4; t++) {
            float v = sp[sr * 4 + t] + dd[t];
            v = (v >= 0.f) ? v : 0.2f * v;
            m[t] = fmaxf(m[t], v);
        }
    }
#pragma unroll
    for (int o = 16; o > 0; o >>= 1)
#pragma unroll
        for (int t = 0; t < 4; t++)
            m[t] = fmaxf(m[t], __shfl_xor_sync(0xffffffffu, m[t], o));

    float sums[4] = {0.f, 0.f, 0.f, 0.f};
    for (int j = 0; j < dg; j++) {
        int e = eip[st + j];
        int sr = esrc[e];
        float p[4];
#pragma unroll
        for (int t = 0; t < 4; t++) {
            float v = sp[sr * 4 + t] + dd[t];
            v = (v >= 0.f) ? v : 0.2f * v;
            p[t] = expf(v - m[t]);
            sums[t] += p[t];
        }
        const float* hr = h + (size_t)sr * F;
#pragma unroll
        for (int c = 0; c < C; c++) {
            int f = lane + 32 * c;
            acc[c] += hr[f] * p[f / D];
        }
    }
#pragma unroll
    for (int c = 0; c < C; c++) {
        int f = lane + 32 * c;
        float v = acc[c] / (sums[f / D] + 1e-16f);
        out[(size_t)w * F + f] = to_tf32(fmaxf(v, 0.f));
    }
}

// ---------------------------------------------------------------------------
// Semantic attention
// ---------------------------------------------------------------------------
__global__ void semantic_kernel(const float* __restrict__ wsum,
                                const float* __restrict__ q,
                                float* __restrict__ attn, int F, float invN)
{
    __shared__ float sh0[256], sh1[256];
    int t = threadIdx.x;
    float p0 = 0.f, p1 = 0.f;
    for (int f = t; f < F; f += 256) {
        float qf = q[f];
        p0 += wsum[f] * invN * qf;
        p1 += wsum[F + f] * invN * qf;
    }
    sh0[t] = p0; sh1[t] = p1;
    __syncthreads();
    for (int s = 128; s > 0; s >>= 1) {
        if (t < s) { sh0[t] += sh0[t + s]; sh1[t] += sh1[t + s]; }
        __syncthreads();
    }
    if (t == 0) {
        float m  = fmaxf(sh0[0], sh1[0]);
        float e0 = expf(sh0[0] - m);
        float e1 = expf(sh1[0] - m);
        float inv = 1.f / (e0 + e1);
        attn[0] = e0 * inv;
        attn[1] = e1 * inv;
    }
}

// ---------------------------------------------------------------------------
// Final combine + pool (fused; inputs already relu'd), count, head
// ---------------------------------------------------------------------------
__global__ void combine_pool_kernel(const float* __restrict__ o0,
                                    const float* __restrict__ o1,
                                    const float* __restrict__ attn,
                                    const int* __restrict__ batch,
                                    float* __restrict__ pool, int n, int F)
{
    long i = (long)blockIdx.x * blockDim.x + threadIdx.x;
    if (i >= (long)n * F) return;
    int node = (int)(i / F);
    int f    = (int)(i % F);
    float v = attn[0] * o0[i] + attn[1] * o1[i];
    atomicAdd(&pool[batch[node] * F + f], v);
}

__global__ void count_kernel(const int* __restrict__ batch,
                             float* __restrict__ cnt, int n)
{
    int i = blockIdx.x * blockDim.x + threadIdx.x;
    if (i < n) atomicAdd(&cnt[batch[i]], 1.f);
}

__global__ void head_kernel(const float* __restrict__ pool,
                            const float* __restrict__ cnt,
                            const float* __restrict__ d1w,
                            const float* __restrict__ d1b,
                            const float* __restrict__ gma,
                            const float* __restrict__ bta,
                            const float* __restrict__ mean,
                            const float* __restrict__ var,
                            const float* __restrict__ d2w,
                            const float* __restrict__ d2b,
                            float* __restrict__ out)
{
    int g = blockIdx.x;
    int j = threadIdx.x;
    float c = fmaxf(cnt[g], 1.f);
    float inv = 1.f / c;
    float acc = d1b[j];
    for (int k = 0; k < F2; k++)
        acc += (pool[g * F2 + k] * inv) * d1w[k * 64 + j];
    acc = (acc - mean[j]) * rsqrtf(var[j] + 1e-5f) * gma[j] + bta[j];
    acc = (acc >= 0.f) ? acc : 0.1f * acc;
    float v = acc * d2w[j];
    __shared__ float red[64];
    red[j] = v;
    __syncthreads();
    for (int s = 32; s > 0; s >>= 1) {
        if (j < s) red[j] += red[j + s];
        __syncthreads();
    }
    if (j == 0) out[g] = red[0] + d2b[0];
}

// ---------------------------------------------------------------------------
// Host orchestration
// ---------------------------------------------------------------------------
static inline int cdiv(long a, int b) { return (int)((a + b - 1) / b); }

extern "C" void kernel_launch(void* const* d_in, const int* in_sizes, int n_in,
                              void* d_out, int out_size)
{
    const float* x       = (const float*)d_in[0];
    const int*   ei0     = (const int*)d_in[1];
    const int*   ei1     = (const int*)d_in[2];
    const int*   batch   = (const int*)d_in[3];
    const float* proj1_w = (const float*)d_in[4];
    const float* proj1_b = (const float*)d_in[5];
    const float* as1_r0  = (const float*)d_in[6];
    const float* ad1_r0  = (const float*)d_in[7];
    const float* as1_r1  = (const float*)d_in[8];
    const float* ad1_r1  = (const float*)d_in[9];
    const float* klin1_w = (const float*)d_in[10];
    const float* klin1_b = (const float*)d_in[11];
    const float* q1      = (const float*)d_in[12];
    const float* proj2_w = (const float*)d_in[13];
    const float* proj2_b = (const float*)d_in[14];
    const float* as2_r0  = (const float*)d_in[15];
    const float* ad2_r0  = (const float*)d_in[16];
    const float* as2_r1  = (const float*)d_in[17];
    const float* ad2_r1  = (const float*)d_in[18];
    const float* klin2_w = (const float*)d_in[19];
    const float* klin2_b = (const float*)d_in[20];
    const float* q2      = (const float*)d_in[21];
    const float* d1_w    = (const float*)d_in[22];
    const float* d1_b    = (const float*)d_in[23];
    const float* bn_g    = (const float*)d_in[24];
    const float* bn_b    = (const float*)d_in[25];
    const float* bn_m    = (const float*)d_in[26];
    const float* bn_v    = (const float*)d_in[27];
    const float* d2_w    = (const float*)d_in[28];
    const float* d2_b    = (const float*)d_in[29];
    float* out = (float*)d_out;

    float *h, *o0, *o1, *xr, *wa, *wb, *wc, *s, *d, *wsum, *attn, *pool, *cnt;
    int *deg, *rowptr, *cursor, *eid, *partials;
    cudaGetSymbolAddress((void**)&h,       g_h);
    cudaGetSymbolAddress((void**)&o0,      g_out0);
    cudaGetSymbolAddress((void**)&o1,      g_out1);
    cudaGetSymbolAddress((void**)&xr,      g_x);
    cudaGetSymbolAddress((void**)&wa,      g_wa);
    cudaGetSymbolAddress((void**)&wb,      g_wb);
    cudaGetSymbolAddress((void**)&wc,      g_wc);
    cudaGetSymbolAddress((void**)&s,       g_s);
    cudaGetSymbolAddress((void**)&d,       g_dd);
    cudaGetSymbolAddress((void**)&wsum,    g_wsum);
    cudaGetSymbolAddress((void**)&attn,    g_attn);
    cudaGetSymbolAddress((void**)&pool,    g_pool);
    cudaGetSymbolAddress((void**)&cnt,     g_cnt);
    cudaGetSymbolAddress((void**)&deg,     g_deg);
    cudaGetSymbolAddress((void**)&rowptr,  g_rowptr);
    cudaGetSymbolAddress((void**)&cursor,  g_cursor);
    cudaGetSymbolAddress((void**)&eid,     g_eid);
    cudaGetSymbolAddress((void**)&partials,g_partials);

    const int n = NNODES, E = NEDGES;
    const int egrid = cdiv(E, 256);
    const int agg_blocks = cdiv(n, 8);

    // ---- pre-rounding + CSR build; launch #6 is proj1 GEMM for ncu ----
    round_copy<<<cdiv((long)n * 128, 256), 256>>>(x, xr, (long)n * 128);      // 1
    round_copy<<<cdiv(128 * 256, 256), 256>>>(proj1_w, wa, 128 * 256);        // 2
    round_copy<<<cdiv(256 * 256, 256), 256>>>(klin1_w, wb, 256 * 256);        // 3
    prep_zero<<<cdiv(2 * n, 256), 256>>>(deg, pool, cnt);                     // 4
    hist_kernel<<<dim3(egrid, 2), 256>>>(ei0, ei1, deg);                      // 5
    {   // 6: proj1 GEMM (fast path)
        dim3 grid(F1 / GBN, cdiv(n, GBM), 1);
        mma_gemm_async<<<grid, 256>>>(xr, nullptr, wa, proj1_b, h,
                                      n, 128, F1, 0, nullptr);
    }
    scan1_kernel<<<dim3(NB, 2), 256>>>(deg, rowptr, partials);
    scan2_kernel<<<2, 256>>>(partials);
    scan3_kernel<<<dim3(NB, 2), 256>>>(rowptr, partials, cursor);
    fillpos_kernel<<<dim3(egrid, 2), 256>>>(ei0, ei1, cursor, eid);
    round_copy<<<cdiv(128 * 128, 256), 256>>>(klin2_w, wc, 128 * 128);

    // ---- Layer 1 (F=256, D=64) ----
    fillk<<<cdiv(2 * F1, 256), 256>>>(wsum, 0.f, 2 * F1);
    node_scores_kernel<<<dim3(cdiv(n * NHEAD, 256), 2), 256>>>(
        h, as1_r0, ad1_r0, as1_r1, ad1_r1, s, d, n, F1, 64);
    agg_kernel<F1, 64><<<dim3(agg_blocks, 2), 256>>>(
        rowptr, deg, eid, ei0, ei1, h, s, d, o0, o1, n);
    {
        dim3 grid(F1 / GBN, cdiv(n, GBM), 2);
        mma_gemm_async<<<grid, 256>>>(o0, o1, wb, klin1_b, nullptr,
                                      n, F1, F1, 1, wsum);
    }
    semantic_kernel<<<1, 256>>>(wsum, q1, attn, F1, 1.f / n);

    // ---- Layer 2 (F=128, D=32); proj2 fuses attn-combine ----
    fillk<<<cdiv(2 * F2, 256), 256>>>(wsum, 0.f, 2 * F2);
    {
        dim3 grid(F2 / GBN, cdiv(n, GBM));
        mma_gemm_combine<<<grid, 256>>>(o0, o1, attn, proj2_w, proj2_b, h,
                                        n, F1, F2);
    }
    node_scores_kernel<<<dim3(cdiv(n * NHEAD, 256), 2), 256>>>(
        h, as2_r0, ad2_r0, as2_r1, ad2_r1, s, d, n, F2, 32);
    agg_kernel<F2, 32><<<dim3(agg_blocks, 2), 256>>>(
        rowptr, deg, eid, ei0, ei1, h, s, d, o0, o1, n);
    {
        dim3 grid(F2 / GBN, cdiv(n, GBM), 2);
        mma_gemm_async<<<grid, 256>>>(o0, o1, wc, klin2_b, nullptr,
                                      n, F2, F2, 1, wsum);
    }
    semantic_kernel<<<1, 256>>>(wsum, q2, attn, F2, 1.f / n);

    // ---- Combine+pool (fused), count, head ----
    combine_pool_kernel<<<cdiv((long)n * F2, 256), 256>>>(
        o0, o1, attn, batch, pool, n, F2);
    count_kernel<<<cdiv(n, 256), 256>>>(batch, cnt, n);
    head_kernel<<<NGRAPH, 64>>>(pool, cnt, d1_w, d1_b, bn_g, bn_b, bn_m, bn_v,
                                d2_w, d2_b, out);
}

// round 7
// speedup vs baseline: 3.3032x; 1.0902x over previous
#include <cuda_runtime.h>
#include <cuda_bf16.h>
#include <cstdint>
#include <math.h>

// Problem constants (match reference)
#define NNODES 50000
#define NEDGES 400000
#define NGRAPH 64
#define NHEAD  4
#define F1 256
#define F2 128
#define NB 196   // ceil(NNODES/256)

// ---------------------------------------------------------------------------
// Device scratch
// ---------------------------------------------------------------------------
__device__ float g_h[NNODES * F1];
__device__ float g_out0[NNODES * F1];
__device__ float g_out1[NNODES * F1];
__device__ float g_x[NNODES * 128];         // tf32-rounded input features
__device__ float g_wa[128 * 256];           // rounded proj1_w
__device__ float g_wb[256 * 256];           // rounded klin1_w
__device__ float g_wc[128 * 128];           // rounded klin2_w
__device__ float g_s[2 * NNODES * NHEAD];
__device__ float g_dd[2 * NNODES * NHEAD];
__device__ float g_wsum[2 * F1];
__device__ float g_attn[2];
__device__ float g_pool[NGRAPH * F2];
__device__ float g_cnt[NGRAPH];
// CSR (by dst), 2 relations; adjacency stores SRC node ids directly
__device__ int g_deg[2 * NNODES];
__device__ int g_rowptr[2 * NNODES];
__device__ int g_cursor[2 * NNODES];
__device__ int g_adj[2 * NEDGES];
__device__ int g_partials[2 * NB];

// ---------------------------------------------------------------------------
// Helpers
// ---------------------------------------------------------------------------
__device__ __forceinline__ unsigned to_tf32_bits(float x) {
    unsigned r;
    asm("cvt.rna.tf32.f32 %0, %1;" : "=r"(r) : "f"(x));
    return r;
}
__device__ __forceinline__ float to_tf32(float x) {
    return __uint_as_float(to_tf32_bits(x));
}
__device__ __forceinline__ float tanh_fast(float x) {
    float y;
    asm("tanh.approx.f32 %0, %1;" : "=f"(y) : "f"(x));
    return y;
}

__device__ __forceinline__ void mma_tf32(float c[4],
                                         const unsigned a[4],
                                         const unsigned b[2]) {
    asm volatile(
        "mma.sync.aligned.m16n8k8.row.col.f32.tf32.tf32.f32 "
        "{%0,%1,%2,%3}, {%4,%5,%6,%7}, {%8,%9}, {%0,%1,%2,%3};"
        : "+f"(c[0]), "+f"(c[1]), "+f"(c[2]), "+f"(c[3])
        : "r"(a[0]), "r"(a[1]), "r"(a[2]), "r"(a[3]),
          "r"(b[0]), "r"(b[1]));
}

__device__ __forceinline__ void cp_async16(uint32_t s, const void* g, bool v) {
    int sz = v ? 16 : 0;
    asm volatile("cp.async.ca.shared.global [%0], [%1], 16, %2;"
                 :: "r"(s), "l"(g), "r"(sz));
}
__device__ __forceinline__ void cp_commit() {
    asm volatile("cp.async.commit_group;" ::: "memory");
}
template<int N>
__device__ __forceinline__ void cp_wait() {
    asm volatile("cp.async.wait_group %0;" :: "n"(N) : "memory");
}

__global__ void fillk(float* __restrict__ p, float v, long n) {
    long i = (long)blockIdx.x * blockDim.x + threadIdx.x;
    if (i < n) p[i] = v;
}

__global__ void round_copy(const float* __restrict__ in,
                           float* __restrict__ out, long n) {
    long i = (long)blockIdx.x * blockDim.x + threadIdx.x;
    if (i < n) out[i] = to_tf32(in[i]);
}

// ---------------------------------------------------------------------------
// CSR build kernels
// ---------------------------------------------------------------------------
__global__ void prep_zero(int* __restrict__ deg, float* __restrict__ pool,
                          float* __restrict__ cnt) {
    int i = blockIdx.x * 256 + threadIdx.x;
    if (i < 2 * NNODES) deg[i] = 0;
    if (i < NGRAPH * F2) pool[i] = 0.f;
    if (i < NGRAPH) cnt[i] = 0.f;
}

__global__ void hist_kernel(const int* __restrict__ ei0,
                            const int* __restrict__ ei1,
                            int* __restrict__ deg) {
    int r = blockIdx.y;
    const int* dst = (r == 0 ? ei0 : ei1) + NEDGES;
    int e = blockIdx.x * 256 + threadIdx.x;
    if (e < NEDGES) atomicAdd(&deg[r * NNODES + dst[e]], 1);
}

__global__ void scan1_kernel(const int* __restrict__ deg,
                             int* __restrict__ rowptr,
                             int* __restrict__ partials) {
    int r = blockIdx.y, b = blockIdx.x, t = threadIdx.x;
    int i = b * 256 + t;
    __shared__ int sh[256];
    int v = (i < NNODES) ? deg[r * NNODES + i] : 0;
    sh[t] = v;
    __syncthreads();
    for (int off = 1; off < 256; off <<= 1) {
        int x = (t >= off) ? sh[t - off] : 0;
        __syncthreads();
        sh[t] += x;
        __syncthreads();
    }
    if (i < NNODES) rowptr[r * NNODES + i] = sh[t] - v;  // exclusive
    if (t == 255) partials[r * NB + b] = sh[t];
}

__global__ void scan2_kernel(int* __restrict__ partials) {
    int r = blockIdx.x, t = threadIdx.x;
    __shared__ int sh[256];
    int v = (t < NB) ? partials[r * NB + t] : 0;
    sh[t] = v;
    __syncthreads();
    for (int off = 1; off < 256; off <<= 1) {
        int x = (t >= off) ? sh[t - off] : 0;
        __syncthreads();
        sh[t] += x;
        __syncthreads();
    }
    if (t < NB) partials[r * NB + t] = sh[t] - v;  // exclusive
}

__global__ void scan3_kernel(int* __restrict__ rowptr,
                             const int* __restrict__ partials,
                             int* __restrict__ cursor) {
    int r = blockIdx.y;
    int i = blockIdx.x * 256 + threadIdx.x;
    if (i < NNODES) {
        int v = rowptr[r * NNODES + i] + partials[r * NB + blockIdx.x];
        rowptr[r * NNODES + i] = v;
        cursor[r * NNODES + i] = v;
    }
}

// Stores SRC node id into the adjacency (one less indirection in agg)
__global__ void fillpos_kernel(const int* __restrict__ ei0,
                               const int* __restrict__ ei1,
                               int* __restrict__ cursor,
                               int* __restrict__ adj) {
    int r = blockIdx.y;
    const int* ei = (r == 0 ? ei0 : ei1);
    int e = blockIdx.x * 256 + threadIdx.x;
    if (e < NEDGES) {
        int pos = atomicAdd(&cursor[r * NNODES + ei[NEDGES + e]], 1);
        adj[r * NEDGES + pos] = ei[e];
    }
}

// ---------------------------------------------------------------------------
// Fast TF32 GEMM (cp.async 4-stage). A and W MUST be pre-rounded to tf32.
// C[M,F] = A[M,K] @ W[K,F] (+bias)
// mode 0: write C = acc + bias; mode 1: colsum += sum_m tanh(acc + bias)
// grid.z selects A0/A1 (batched klin GEMMs); colsum offset = z*F.
// ---------------------------------------------------------------------------
#define GBM 128
#define GBN 128
#define FBK 8
#define FA_STRIDE 12
#define FB_STRIDE 136
#define FSTAGES 4

__global__ __launch_bounds__(256) void mma_gemm_async(
    const float* __restrict__ A0, const float* __restrict__ A1,
    const float* __restrict__ W,
    const float* __restrict__ bias, float* __restrict__ C,
    int M, int K, int F, int mode, float* __restrict__ colsum)
{
    __shared__ float As[FSTAGES][GBM][FA_STRIDE];   // 4*128*12*4 = 24576 B
    __shared__ float Bs[FSTAGES][FBK][FB_STRIDE];   // 4*8*136*4  = 17408 B

    const float* __restrict__ A = (blockIdx.z == 0) ? A0 : A1;
    float* cs = (mode == 1) ? colsum + blockIdx.z * F : nullptr;

    const int tid  = threadIdx.x;
    const int lane = tid & 31;
    const int warp = tid >> 5;
    const int wm   = warp & 1;
    const int wn   = warp >> 1;
    const int gid  = lane >> 2;
    const int tig  = lane & 3;

    const int rowBase = blockIdx.y * GBM;
    const int colBase = blockIdx.x * GBN;

    const int a_r = tid >> 1;          // 0..127
    const int a_c = (tid & 1) * 4;     // 0 or 4
    const int b_r = tid >> 5;          // 0..7
    const int b_c = (tid & 31) * 4;    // 0..124
    const bool a_valid = (rowBase + a_r) < M;
    const uint32_t a_sbase = (uint32_t)__cvta_generic_to_shared(&As[0][a_r][a_c]);
    const uint32_t b_sbase = (uint32_t)__cvta_generic_to_shared(&Bs[0][b_r][b_c]);
    const size_t a_goff = (size_t)(rowBase + a_r) * K + a_c;
    const size_t b_goff = (size_t)b_r * F + colBase + b_c;
    const uint32_t a_stage_b = GBM * FA_STRIDE * 4;
    const uint32_t b_stage_b = FBK * FB_STRIDE * 4;

    float acc[4][4][4];
#pragma unroll
    for (int mt = 0; mt < 4; mt++)
#pragma unroll
        for (int nt = 0; nt < 4; nt++)
#pragma unroll
            for (int i = 0; i < 4; i++) acc[mt][nt][i] = 0.f;

    const int KT = K / FBK;

#define ISSUE(stage, kt_) do {                                              \
        cp_async16(a_sbase + (stage) * a_stage_b,                           \
                   A + a_goff + (size_t)(kt_) * FBK, a_valid);              \
        cp_async16(b_sbase + (stage) * b_stage_b,                           \
                   W + b_goff + (size_t)(kt_) * FBK * F, true);             \
        cp_commit();                                                        \
    } while (0)

    ISSUE(0, 0);
    ISSUE(1, 1);
    ISSUE(2, 2);

    for (int kt = 0; kt < KT; kt++) {
        const int rem = KT - kt - 1;
        if (rem >= 2)      cp_wait<2>();
        else if (rem == 1) cp_wait<1>();
        else               cp_wait<0>();
        __syncthreads();

        const int buf = kt & (FSTAGES - 1);
        unsigned afr[4][4], bfr[4][2];
#pragma unroll
        for (int mt = 0; mt < 4; mt++) {
            int r = wm * 64 + mt * 16 + gid;
            afr[mt][0] = __float_as_uint(As[buf][r][tig]);
            afr[mt][1] = __float_as_uint(As[buf][r + 8][tig]);
            afr[mt][2] = __float_as_uint(As[buf][r][tig + 4]);
            afr[mt][3] = __float_as_uint(As[buf][r + 8][tig + 4]);
        }
#pragma unroll
        for (int nt = 0; nt < 4; nt++) {
            int c = wn * 32 + nt * 8 + gid;
            bfr[nt][0] = __float_as_uint(Bs[buf][tig][c]);
            bfr[nt][1] = __float_as_uint(Bs[buf][tig + 4][c]);
        }
#pragma unroll
        for (int mt = 0; mt < 4; mt++)
#pragma unroll
            for (int nt = 0; nt < 4; nt++)
                mma_tf32(acc[mt][nt], afr[mt], bfr[nt]);

        if (kt + FSTAGES - 1 < KT)
            ISSUE((kt + FSTAGES - 1) & (FSTAGES - 1), kt + FSTAGES - 1);
    }
#undef ISSUE

    if (mode == 0) {
#pragma unroll
        for (int mt = 0; mt < 4; mt++) {
            int r0 = rowBase + wm * 64 + mt * 16 + gid;
            int r1 = r0 + 8;
#pragma unroll
            for (int nt = 0; nt < 4; nt++) {
                int gc = colBase + wn * 32 + nt * 8 + tig * 2;
                float b0 = bias[gc], b1 = bias[gc + 1];
                if (r0 < M) {
                    float2 v = make_float2(acc[mt][nt][0] + b0, acc[mt][nt][1] + b1);
                    *reinterpret_cast<float2*>(&C[(size_t)r0 * F + gc]) = v;
                }
                if (r1 < M) {
                    float2 v = make_float2(acc[mt][nt][2] + b0, acc[mt][nt][3] + b1);
                    *reinterpret_cast<float2*>(&C[(size_t)r1 * F + gc]) = v;
                }
            }
        }
    } else {
#pragma unroll
        for (int nt = 0; nt < 4; nt++) {
            int gc = colBase + wn * 32 + nt * 8 + tig * 2;
            float b0 = bias[gc], b1 = bias[gc + 1];
            float csA = 0.f, csB = 0.f;
#pragma unroll
            for (int mt = 0; mt < 4; mt++) {
                int r0 = rowBase + wm * 64 + mt * 16 + gid;
                int r1 = r0 + 8;
                if (r0 < M) {
                    csA += tanh_fast(acc[mt][nt][0] + b0);
                    csB += tanh_fast(acc[mt][nt][1] + b1);
                }
                if (r1 < M) {
                    csA += tanh_fast(acc[mt][nt][2] + b0);
                    csB += tanh_fast(acc[mt][nt][3] + b1);
                }
            }
            atomicAdd(&cs[gc], csA);
            atomicAdd(&cs[gc + 1], csB);
        }
    }
}

// ---------------------------------------------------------------------------
// Register-staging TF32 GEMM, used only for proj2 (fused attn-combine on A).
// A-path: at0*A + at1*A2 (inputs already relu'd), rounded at staging.
// ---------------------------------------------------------------------------
#define GBK 16
#define A_STRIDE 20
#define B_STRIDE 136

__global__ __launch_bounds__(256) void mma_gemm_combine(
    const float* __restrict__ A, const float* __restrict__ A2,
    const float* __restrict__ attnp,
    const float* __restrict__ W,
    const float* __restrict__ bias, float* __restrict__ C,
    int M, int K, int F)
{
    __shared__ float As[2][GBM][A_STRIDE];
    __shared__ float Bs[2][GBK][B_STRIDE];

    const int tid  = threadIdx.x;
    const int lane = tid & 31;
    const int warp = tid >> 5;
    const int wm   = warp & 1;
    const int wn   = warp >> 1;
    const int gid  = lane >> 2;
    const int tig  = lane & 3;

    const int rowBase = blockIdx.y * GBM;
    const int colBase = blockIdx.x * GBN;

    const float at0 = attnp[0], at1 = attnp[1];

    float acc[4][4][4];
#pragma unroll
    for (int mt = 0; mt < 4; mt++)
#pragma unroll
        for (int nt = 0; nt < 4; nt++)
#pragma unroll
            for (int i = 0; i < 4; i++) acc[mt][nt][i] = 0.f;

    const int a_r0 = tid >> 2;
    const int a_c0 = (tid & 3) * 4;
    const int b_k0 = tid >> 5;
    const int b_c0 = (tid & 31) * 4;

    const int KT = K / GBK;
    float4 ra[2], rb[2];

#define LDA(gr, off) ({                                                      \
        float4 v = *reinterpret_cast<const float4*>(A + (off));              \
        float4 u = *reinterpret_cast<const float4*>(A2 + (off));             \
        v.x = at0 * v.x + at1 * u.x;  v.y = at0 * v.y + at1 * u.y;           \
        v.z = at0 * v.z + at1 * u.z;  v.w = at0 * v.w + at1 * u.w;  v; })

    {
#pragma unroll
        for (int i = 0; i < 2; i++) {
            int gr = rowBase + a_r0 + i * 64;
            ra[i] = (gr < M) ? LDA(gr, (size_t)gr * K + a_c0)
                             : make_float4(0.f, 0.f, 0.f, 0.f);
            int kr = b_k0 + i * 8;
            rb[i] = *reinterpret_cast<const float4*>(&W[(size_t)kr * F + colBase + b_c0]);
        }
#pragma unroll
        for (int i = 0; i < 2; i++) {
            float4 v;
            v.x = to_tf32(ra[i].x); v.y = to_tf32(ra[i].y);
            v.z = to_tf32(ra[i].z); v.w = to_tf32(ra[i].w);
            *reinterpret_cast<float4*>(&As[0][a_r0 + i * 64][a_c0]) = v;
            float4 w;
            w.x = to_tf32(rb[i].x); w.y = to_tf32(rb[i].y);
            w.z = to_tf32(rb[i].z); w.w = to_tf32(rb[i].w);
            *reinterpret_cast<float4*>(&Bs[0][b_k0 + i * 8][b_c0]) = w;
        }
    }
    __syncthreads();

    for (int kt = 0; kt < KT; kt++) {
        const int buf = kt & 1;
        if (kt + 1 < KT) {
            const int k0 = (kt + 1) * GBK;
#pragma unroll
            for (int i = 0; i < 2; i++) {
                int gr = rowBase + a_r0 + i * 64;
                ra[i] = (gr < M) ? LDA(gr, (size_t)gr * K + k0 + a_c0)
                                 : make_float4(0.f, 0.f, 0.f, 0.f);
                int kr = b_k0 + i * 8;
                rb[i] = *reinterpret_cast<const float4*>(&W[(size_t)(k0 + kr) * F + colBase + b_c0]);
            }
        }
#pragma unroll
        for (int ks = 0; ks < 2; ks++) {
            const int kb = ks * 8;
            unsigned afr[4][4], bfr[4][2];
#pragma unroll
            for (int mt = 0; mt < 4; mt++) {
                int r = wm * 64 + mt * 16 + gid;
                afr[mt][0] = __float_as_uint(As[buf][r][kb + tig]);
                afr[mt][1] = __float_as_uint(As[buf][r + 8][kb + tig]);
                afr[mt][2] = __float_as_uint(As[buf][r][kb + tig + 4]);
                afr[mt][3] = __float_as_uint(As[buf][r + 8][kb + tig + 4]);
            }
#pragma unroll
            for (int nt = 0; nt < 4; nt++) {
                int c = wn * 32 + nt * 8 + gid;
                bfr[nt][0] = __float_as_uint(Bs[buf][kb + tig][c]);
                bfr[nt][1] = __float_as_uint(Bs[buf][kb + tig + 4][c]);
            }
#pragma unroll
            for (int mt = 0; mt < 4; mt++)
#pragma unroll
                for (int nt = 0; nt < 4; nt++)
                    mma_tf32(acc[mt][nt], afr[mt], bfr[nt]);
        }
        if (kt + 1 < KT) {
            const int nbuf = (kt + 1) & 1;
#pragma unroll
            for (int i = 0; i < 2; i++) {
                float4 v;
                v.x = to_tf32(ra[i].x); v.y = to_tf32(ra[i].y);
                v.z = to_tf32(ra[i].z); v.w = to_tf32(ra[i].w);
                *reinterpret_cast<float4*>(&As[nbuf][a_r0 + i * 64][a_c0]) = v;
                float4 w;
                w.x = to_tf32(rb[i].x); w.y = to_tf32(rb[i].y);
                w.z = to_tf32(rb[i].z); w.w = to_tf32(rb[i].w);
                *reinterpret_cast<float4*>(&Bs[nbuf][b_k0 + i * 8][b_c0]) = w;
            }
            __syncthreads();
        }
    }
#undef LDA

#pragma unroll
    for (int mt = 0; mt < 4; mt++) {
        int r0 = rowBase + wm * 64 + mt * 16 + gid;
        int r1 = r0 + 8;
#pragma unroll
        for (int nt = 0; nt < 4; nt++) {
            int gc = colBase + wn * 32 + nt * 8 + tig * 2;
            float b0 = bias[gc], b1 = bias[gc + 1];
            if (r0 < M) {
                float2 v = make_float2(acc[mt][nt][0] + b0, acc[mt][nt][1] + b1);
                *reinterpret_cast<float2*>(&C[(size_t)r0 * F + gc]) = v;
            }
            if (r1 < M) {
                float2 v = make_float2(acc[mt][nt][2] + b0, acc[mt][nt][3] + b1);
                *reinterpret_cast<float2*>(&C[(size_t)r1 * F + gc]) = v;
            }
        }
    }
}

// ---------------------------------------------------------------------------
// Per-(node,head) attention scores, both relations in one launch (grid.y)
// ---------------------------------------------------------------------------
__global__ void node_scores_kernel(const float* __restrict__ h,
                                   const float* __restrict__ as0,
                                   const float* __restrict__ ad0,
                                   const float* __restrict__ as1,
                                   const float* __restrict__ ad1,
                                   float* __restrict__ s, float* __restrict__ d,
                                   int n, int F, int D)
{
    int r = blockIdx.y;
    const float* asrc = r == 0 ? as0 : as1;
    const float* adst = r == 0 ? ad0 : ad1;
    int idx = blockIdx.x * blockDim.x + threadIdx.x;
    if (idx >= n * NHEAD) return;
    int node = idx / NHEAD;
    int hh   = idx % NHEAD;
    const float* hp = h + (size_t)node * F + hh * D;
    const float* ap = asrc + hh * D;
    const float* bp = adst + hh * D;
    float ss = 0.f, dd = 0.f;
    for (int i = 0; i < D; i++) {
        float v = hp[i];
        ss += v * ap[i];
        dd += v * bp[i];
    }
    s[r * n * NHEAD + idx] = ss;
    d[r * n * NHEAD + idx] = dd;
}

// ---------------------------------------------------------------------------
// Gather-aggregate: warp per dst node, both relations (grid.y).
// Adjacency stores src ids directly. Writes tf32(relu(out)).
// ---------------------------------------------------------------------------
template<int F, int D>
__global__ __launch_bounds__(256) void agg_kernel(
    const int* __restrict__ rowptr, const int* __restrict__ deg,
    const int* __restrict__ adjacency,
    const float* __restrict__ h, const float* __restrict__ s,
    const float* __restrict__ dvals,
    float* __restrict__ out0, float* __restrict__ out1, int n)
{
    const int r = blockIdx.y;
    float* __restrict__ out = r == 0 ? out0 : out1;
    const int* rp = rowptr + r * n;
    const int* dgp = deg + r * n;
    const int* __restrict__ adj = adjacency + r * NEDGES;
    const float* sp = s + (size_t)r * n * NHEAD;
    const float* dp = dvals + (size_t)r * n * NHEAD;

    int w = blockIdx.x * (blockDim.x >> 5) + (threadIdx.x >> 5);
    int lane = threadIdx.x & 31;
    if (w >= n) return;
    const int dg = dgp[w];
    const int st = rp[w];
    constexpr int C = F / 32;
    float acc[C];
#pragma unroll
    for (int c = 0; c < C; c++) acc[c] = 0.f;
    float dd[4];
#pragma unroll
    for (int t = 0; t < 4; t++) dd[t] = dp[w * 4 + t];

    float m[4] = {-1e30f, -1e30f, -1e30f, -1e30f};
    for (int j = lane; j < dg; j += 32) {
        int sr = adj[st + j];
#pragma unroll
        for (int t = 0; t < 4; t++) {
            float v = sp[sr * 4 + t] + dd[t];
            v = (v >= 0.f) ? v : 0.2f * v;
            m[t] = fmaxf(m[t], v);
        }
    }
#pragma unroll
    for (int o = 16; o > 0; o >>= 1)
#pragma unroll
        for (int t = 0; t < 4; t++)
            m[t] = fmaxf(m[t], __shfl_xor_sync(0xffffffffu, m[t], o));

    float sums[4] = {0.f, 0.f, 0.f, 0.f};
    for (int j = 0; j < dg; j++) {
        int sr = adj[st + j];
        float p[4];
#pragma unroll
        for (int t = 0; t < 4; t++) {
            float v = sp[sr * 4 + t] + dd[t];
            v = (v >= 0.f) ? v : 0.2f * v;
            p[t] = __expf(v - m[t]);
            sums[t] += p[t];
        }
        const float* hr = h + (size_t)sr * F;
#pragma unroll
        for (int c = 0; c < C; c++) {
            int f = lane + 32 * c;
            acc[c] += hr[f] * p[f / D];
        }
    }
#pragma unroll
    for (int c = 0; c < C; c++) {
        int f = lane + 32 * c;
        float v = acc[c] / (sums[f / D] + 1e-16f);
        out[(size_t)w * F + f] = to_tf32(fmaxf(v, 0.f));
    }
}

// ---------------------------------------------------------------------------
// Semantic attention
// ---------------------------------------------------------------------------
__global__ void semantic_kernel(const float* __restrict__ wsum,
                                const float* __restrict__ q,
                                float* __restrict__ attn, int F, float invN)
{
    __shared__ float sh0[256], sh1[256];
    int t = threadIdx.x;
    float p0 = 0.f, p1 = 0.f;
    for (int f = t; f < F; f += 256) {
        float qf = q[f];
        p0 += wsum[f] * invN * qf;
        p1 += wsum[F + f] * invN * qf;
    }
    sh0[t] = p0; sh1[t] = p1;
    __syncthreads();
    for (int s = 128; s > 0; s >>= 1) {
        if (t < s) { sh0[t] += sh0[t + s]; sh1[t] += sh1[t + s]; }
        __syncthreads();
    }
    if (t == 0) {
        float m  = fmaxf(sh0[0], sh1[0]);
        float e0 = expf(sh0[0] - m);
        float e1 = expf(sh1[0] - m);
        float inv = 1.f / (e0 + e1);
        attn[0] = e0 * inv;
        attn[1] = e1 * inv;
    }
}

// ---------------------------------------------------------------------------
// Final combine + pool (fused; inputs already relu'd), count, head
// ---------------------------------------------------------------------------
__global__ void combine_pool_kernel(const float* __restrict__ o0,
                                    const float* __restrict__ o1,
                                    const float* __restrict__ attn,
                                    const int* __restrict__ batch,
                                    float* __restrict__ pool, int n, int F)
{
    long i = (long)blockIdx.x * blockDim.x + threadIdx.x;
    if (i >= (long)n * F) return;
    int node = (int)(i / F);
    int f    = (int)(i % F);
    float v = attn[0] * o0[i] + attn[1] * o1[i];
    atomicAdd(&pool[batch[node] * F + f], v);
}

__global__ void count_kernel(const int* __restrict__ batch,
                             float* __restrict__ cnt, int n)
{
    int i = blockIdx.x * blockDim.x + threadIdx.x;
    if (i < n) atomicAdd(&cnt[batch[i]], 1.f);
}

__global__ void head_kernel(const float* __restrict__ pool,
                            const float* __restrict__ cnt,
                            const float* __restrict__ d1w,
                            const float* __restrict__ d1b,
                            const float* __restrict__ gma,
                            const float* __restrict__ bta,
                            const float* __restrict__ mean,
                            const float* __restrict__ var,
                            const float* __restrict__ d2w,
                            const float* __restrict__ d2b,
                            float* __restrict__ out)
{
    int g = blockIdx.x;
    int j = threadIdx.x;
    float c = fmaxf(cnt[g], 1.f);
    float inv = 1.f / c;
    float acc = d1b[j];
    for (int k = 0; k < F2; k++)
        acc += (pool[g * F2 + k] * inv) * d1w[k * 64 + j];
    acc = (acc - mean[j]) * rsqrtf(var[j] + 1e-5f) * gma[j] + bta[j];
    acc = (acc >= 0.f) ? acc : 0.1f * acc;
    float v = acc * d2w[j];
    __shared__ float red[64];
    red[j] = v;
    __syncthreads();
    for (int s = 32; s > 0; s >>= 1) {
        if (j < s) red[j] += red[j + s];
        __syncthreads();
    }
    if (j == 0) out[g] = red[0] + d2b[0];
}

// ---------------------------------------------------------------------------
// Host orchestration
// ---------------------------------------------------------------------------
static inline int cdiv(long a, int b) { return (int)((a + b - 1) / b); }

extern "C" void kernel_launch(void* const* d_in, const int* in_sizes, int n_in,
                              void* d_out, int out_size)
{
    const float* x       = (const float*)d_in[0];
    const int*   ei0     = (const int*)d_in[1];
    const int*   ei1     = (const int*)d_in[2];
    const int*   batch   = (const int*)d_in[3];
    const float* proj1_w = (const float*)d_in[4];
    const float* proj1_b = (const float*)d_in[5];
    const float* as1_r0  = (const float*)d_in[6];
    const float* ad1_r0  = (const float*)d_in[7];
    const float* as1_r1  = (const float*)d_in[8];
    const float* ad1_r1  = (const float*)d_in[9];
    const float* klin1_w = (const float*)d_in[10];
    const float* klin1_b = (const float*)d_in[11];
    const float* q1      = (const float*)d_in[12];
    const float* proj2_w = (const float*)d_in[13];
    const float* proj2_b = (const float*)d_in[14];
    const float* as2_r0  = (const float*)d_in[15];
    const float* ad2_r0  = (const float*)d_in[16];
    const float* as2_r1  = (const float*)d_in[17];
    const float* ad2_r1  = (const float*)d_in[18];
    const float* klin2_w = (const float*)d_in[19];
    const float* klin2_b = (const float*)d_in[20];
    const float* q2      = (const float*)d_in[21];
    const float* d1_w    = (const float*)d_in[22];
    const float* d1_b    = (const float*)d_in[23];
    const float* bn_g    = (const float*)d_in[24];
    const float* bn_b    = (const float*)d_in[25];
    const float* bn_m    = (const float*)d_in[26];
    const float* bn_v    = (const float*)d_in[27];
    const float* d2_w    = (const float*)d_in[28];
    const float* d2_b    = (const float*)d_in[29];
    float* out = (float*)d_out;

    float *h, *o0, *o1, *xr, *wa, *wb, *wc, *s, *d, *wsum, *attn, *pool, *cnt;
    int *deg, *rowptr, *cursor, *adj, *partials;
    cudaGetSymbolAddress((void**)&h,       g_h);
    cudaGetSymbolAddress((void**)&o0,      g_out0);
    cudaGetSymbolAddress((void**)&o1,      g_out1);
    cudaGetSymbolAddress((void**)&xr,      g_x);
    cudaGetSymbolAddress((void**)&wa,      g_wa);
    cudaGetSymbolAddress((void**)&wb,      g_wb);
    cudaGetSymbolAddress((void**)&wc,      g_wc);
    cudaGetSymbolAddress((void**)&s,       g_s);
    cudaGetSymbolAddress((void**)&d,       g_dd);
    cudaGetSymbolAddress((void**)&wsum,    g_wsum);
    cudaGetSymbolAddress((void**)&attn,    g_attn);
    cudaGetSymbolAddress((void**)&pool,    g_pool);
    cudaGetSymbolAddress((void**)&cnt,     g_cnt);
    cudaGetSymbolAddress((void**)&deg,     g_deg);
    cudaGetSymbolAddress((void**)&rowptr,  g_rowptr);
    cudaGetSymbolAddress((void**)&cursor,  g_cursor);
    cudaGetSymbolAddress((void**)&adj,     g_adj);
    cudaGetSymbolAddress((void**)&partials,g_partials);

    const int n = NNODES, E = NEDGES;
    const int egrid = cdiv(E, 256);
    const int agg_blocks = cdiv(n, 8);

    // ---- launches 1-3: rounding; launch #4 = proj1 GEMM (ncu capture) ----
    round_copy<<<cdiv((long)n * 128, 256), 256>>>(x, xr, (long)n * 128);      // 1
    round_copy<<<cdiv(128 * 256, 256), 256>>>(proj1_w, wa, 128 * 256);        // 2
    round_copy<<<cdiv(256 * 256, 256), 256>>>(klin1_w, wb, 256 * 256);        // 3
    {   // 4: proj1 GEMM (profile target)
        dim3 grid(F1 / GBN, cdiv(n, GBM), 1);
        mma_gemm_async<<<grid, 256>>>(xr, nullptr, wa, proj1_b, h,
                                      n, 128, F1, 0, nullptr);
    }
    prep_zero<<<cdiv(2 * n, 256), 256>>>(deg, pool, cnt);
    hist_kernel<<<dim3(egrid, 2), 256>>>(ei0, ei1, deg);
    scan1_kernel<<<dim3(NB, 2), 256>>>(deg, rowptr, partials);
    scan2_kernel<<<2, 256>>>(partials);
    scan3_kernel<<<dim3(NB, 2), 256>>>(rowptr, partials, cursor);
    fillpos_kernel<<<dim3(egrid, 2), 256>>>(ei0, ei1, cursor, adj);
    round_copy<<<cdiv(128 * 128, 256), 256>>>(klin2_w, wc, 128 * 128);

    // ---- Layer 1 (F=256, D=64) ----
    fillk<<<cdiv(2 * F1, 256), 256>>>(wsum, 0.f, 2 * F1);
    node_scores_kernel<<<dim3(cdiv(n * NHEAD, 256), 2), 256>>>(
        h, as1_r0, ad1_r0, as1_r1, ad1_r1, s, d, n, F1, 64);
    agg_kernel<F1, 64><<<dim3(agg_blocks, 2), 256>>>(
        rowptr, deg, adj, h, s, d, o0, o1, n);
    {
        dim3 grid(F1 / GBN, cdiv(n, GBM), 2);
        mma_gemm_async<<<grid, 256>>>(o0, o1, wb, klin1_b, nullptr,
                                      n, F1, F1, 1, wsum);
    }
    semantic_kernel<<<1, 256>>>(wsum, q1, attn, F1, 1.f / n);

    // ---- Layer 2 (F=128, D=32); proj2 fuses attn-combine ----
    fillk<<<cdiv(2 * F2, 256), 256>>>(wsum, 0.f, 2 * F2);
    {
        dim3 grid(F2 / GBN, cdiv(n, GBM));
        mma_gemm_combine<<<grid, 256>>>(o0, o1, attn, proj2_w, proj2_b, h,
                                        n, F1, F2);
    }
    node_scores_kernel<<<dim3(cdiv(n * NHEAD, 256), 2), 256>>>(
        h, as2_r0, ad2_r0, as2_r1, ad2_r1, s, d, n, F2, 32);
    agg_kernel<F2, 32><<<dim3(agg_blocks, 2), 256>>>(
        rowptr, deg, adj, h, s, d, o0, o1, n);
    {
        dim3 grid(F2 / GBN, cdiv(n, GBM), 2);
        mma_gemm_async<<<grid, 256>>>(o0, o1, wc, klin2_b, nullptr,
                                      n, F2, F2, 1, wsum);
    }
    semantic_kernel<<<1, 256>>>(wsum, q2, attn, F2, 1.f / n);

    // ---- Combine+pool (fused), count, head ----
    combine_pool_kernel<<<cdiv((long)n * F2, 256), 256>>>(
        o0, o1, attn, batch, pool, n, F2);
    count_kernel<<<cdiv(n, 256), 256>>>(batch, cnt, n);
    head_kernel<<<NGRAPH, 64>>>(pool, cnt, d1_w, d1_b, bn_g, bn_b, bn_m, bn_v,
                                d2_w, d2_b, out);
}